// round 3
// baseline (speedup 1.0000x reference)
#include <cuda_runtime.h>

#define B_SZ 16
#define M_SZ 128
#define T_SZ 2048
#define H_SZ 512

// Scratch (device globals: allocation-free per harness rules)
__device__ float g_H[(size_t)B_SZ * H_SZ * T_SZ];   // 67 MB  hidden activations
__device__ float g_Q[(size_t)B_SZ * M_SZ * T_SZ];   // 16.8 MB
__device__ float g_K[(size_t)B_SZ * M_SZ * T_SZ];   // 16.8 MB
__device__ float g_A[(size_t)B_SZ * M_SZ * T_SZ];   // 16.8 MB attn_in

// ---------------------------------------------------------------------------
// Batched SGEMM: C[bz] = A (Md x K, shared) @ B[bz] (K x N) + bias, opt leaky
// 128x128 block tile, BK=8, 256 threads, 8x8 register tile.
// ---------------------------------------------------------------------------
template<int ACT>
__global__ void __launch_bounds__(256) sgemm_bias(
    const float* __restrict__ A, const float* __restrict__ B,
    const float* __restrict__ bias, float* __restrict__ C,
    int Md, int N, int K, long strideB, long strideC, int ldc)
{
    __shared__ float As[8][128];
    __shared__ float Bs[8][128];
    const int bz = blockIdx.z;
    const float* Bp = B + (long)bz * strideB;
    float* Cp = C + (long)bz * strideC;
    const int m0 = blockIdx.y * 128;
    const int n0 = blockIdx.x * 128;
    const int tid = threadIdx.x;
    const int tx = tid & 15;          // n-group
    const int ty = tid >> 4;          // m-group
    const int arow = tid >> 1, acol = (tid & 1) * 4;
    const int brow = tid >> 5, bcol = (tid & 31) * 4;

    float acc[8][8];
#pragma unroll
    for (int i = 0; i < 8; i++)
#pragma unroll
        for (int j = 0; j < 8; j++) acc[i][j] = 0.f;

    for (int k0 = 0; k0 < K; k0 += 8) {
        float4 av = *(const float4*)(A + (long)(m0 + arow) * K + k0 + acol);
        float4 bv = *(const float4*)(Bp + (long)(k0 + brow) * N + n0 + bcol);
        __syncthreads();
        As[acol + 0][arow] = av.x;
        As[acol + 1][arow] = av.y;
        As[acol + 2][arow] = av.z;
        As[acol + 3][arow] = av.w;
        *(float4*)(&Bs[brow][bcol]) = bv;
        __syncthreads();
#pragma unroll
        for (int kk = 0; kk < 8; kk++) {
            float4 a0 = *(const float4*)(&As[kk][ty * 8]);
            float4 a1 = *(const float4*)(&As[kk][ty * 8 + 4]);
            float4 b0 = *(const float4*)(&Bs[kk][tx * 8]);
            float4 b1 = *(const float4*)(&Bs[kk][tx * 8 + 4]);
            float ar[8] = {a0.x, a0.y, a0.z, a0.w, a1.x, a1.y, a1.z, a1.w};
            float br[8] = {b0.x, b0.y, b0.z, b0.w, b1.x, b1.y, b1.z, b1.w};
#pragma unroll
            for (int i = 0; i < 8; i++)
#pragma unroll
                for (int j = 0; j < 8; j++)
                    acc[i][j] += ar[i] * br[j];
        }
    }
#pragma unroll
    for (int i = 0; i < 8; i++) {
        int m = m0 + ty * 8 + i;
        float bb = bias[m];
#pragma unroll
        for (int j = 0; j < 8; j++) {
            float v = acc[i][j] + bb;
            if (ACT) v = v > 0.f ? v : 0.01f * v;
            Cp[(long)m * ldc + n0 + tx * 8 + j] = v;
        }
    }
}

// ---------------------------------------------------------------------------
// Fused attention, flash-style. Block = (q-tile of 128, batch).
// S[q,k] = sum_m Q[m,q] K[m,k]; w = exp(exp(S, diag-adjusted));
// out[m,q] = (sum_k w * V[m,k]) / (sum_k w).  No max needed: S std ~0.11.
// SMEM: Qs 128x128, Ks 128x64, Vs 128x65(pad), Ws 128x65(pad), Rs 128.
// ---------------------------------------------------------------------------
#define ATT_SMEM_FLOATS (128 * 128 + 128 * 64 + 128 * 65 + 128 * 65 + 128)
#define ATT_SMEM_BYTES (ATT_SMEM_FLOATS * 4)

__global__ void __launch_bounds__(256) attn_main(
    const float* __restrict__ Q, const float* __restrict__ Kb,
    const float* __restrict__ V, float* __restrict__ O)
{
    extern __shared__ float sm[];
    float* Qs = sm;                   // [m][128q]
    float* Ks = Qs + 128 * 128;       // [m][64k]
    float* Vs = Ks + 128 * 64;        // [m][65]
    float* Ws = Vs + 128 * 65;        // [q][65]
    float* Rs = Ws + 128 * 65;        // [128] running rowsum

    const int b = blockIdx.y;
    const int q0 = blockIdx.x * 128;
    const int tid = threadIdx.x;
    const int tx = tid & 15;
    const int ty = tid >> 4;
    const long bofs = (long)b * M_SZ * T_SZ;
    const float* Qp = Q + bofs + q0;

    for (int i = tid * 4; i < 128 * 128; i += 1024) {
        int m = i >> 7, q = i & 127;
        *(float4*)(Qs + i) = *(const float4*)(Qp + (long)m * T_SZ + q);
    }
    if (tid < 128) Rs[tid] = 0.f;

    float acc[8][8];
#pragma unroll
    for (int i = 0; i < 8; i++)
#pragma unroll
        for (int j = 0; j < 8; j++) acc[i][j] = 0.f;

    const float cdiag = 0.97790291308792045f;  // 1 - 1/sqrt(2048)

    for (int kt = 0; kt < 32; kt++) {
        const int kbase = kt * 64;
        __syncthreads();  // previous readers of Ks/Vs/Ws done (also orders Q load)
        const float* Kp = Kb + bofs + kbase;
        const float* Vp = V + bofs + kbase;
        for (int i = tid * 4; i < 128 * 64; i += 1024) {
            int m = i >> 6, k = i & 63;
            *(float4*)(Ks + m * 64 + k) = *(const float4*)(Kp + (long)m * T_SZ + k);
            float4 vv = *(const float4*)(Vp + (long)m * T_SZ + k);
            Vs[m * 65 + k] = vv.x;
            Vs[m * 65 + k + 1] = vv.y;
            Vs[m * 65 + k + 2] = vv.z;
            Vs[m * 65 + k + 3] = vv.w;
        }
        __syncthreads();

        // S phase: thread covers q = tx + 16i (i<8), k = ty + 16j (j<4)
        float s[8][4];
#pragma unroll
        for (int i = 0; i < 8; i++)
#pragma unroll
            for (int j = 0; j < 4; j++) s[i][j] = 0.f;

#pragma unroll 4
        for (int m = 0; m < 128; m++) {
            float qr[8], kr[4];
#pragma unroll
            for (int i = 0; i < 8; i++) qr[i] = Qs[m * 128 + tx + 16 * i];
#pragma unroll
            for (int j = 0; j < 4; j++) kr[j] = Ks[m * 64 + ty + 16 * j];
#pragma unroll
            for (int i = 0; i < 8; i++)
#pragma unroll
                for (int j = 0; j < 4; j++)
                    s[i][j] += qr[i] * kr[j];
        }
#pragma unroll
        for (int i = 0; i < 8; i++) {
            int gq = q0 + tx + 16 * i;
#pragma unroll
            for (int j = 0; j < 4; j++) {
                int gk = kbase + ty + 16 * j;
                float x = s[i][j];
                if (gq == gk) x *= cdiag;
                Ws[(tx + 16 * i) * 65 + ty + 16 * j] = expf(expf(x));
            }
        }
        __syncthreads();

        // rowsum accumulation (threads 0..127, conflict-free column walk)
        if (tid < 128) {
            float r = 0.f;
#pragma unroll
            for (int k = 0; k < 64; k++) r += Ws[tid * 65 + k];
            Rs[tid] += r;
        }

        // AV phase: thread covers m = ty + 16i (i<8), q = tx + 16j (j<8)
#pragma unroll 4
        for (int k = 0; k < 64; k++) {
            float vr[8], wr[8];
#pragma unroll
            for (int i = 0; i < 8; i++) vr[i] = Vs[(ty + 16 * i) * 65 + k];
#pragma unroll
            for (int j = 0; j < 8; j++) wr[j] = Ws[(tx + 16 * j) * 65 + k];
#pragma unroll
            for (int i = 0; i < 8; i++)
#pragma unroll
                for (int j = 0; j < 8; j++)
                    acc[i][j] += vr[i] * wr[j];
        }
    }
    __syncthreads();  // Rs final

    float rq[8];
#pragma unroll
    for (int j = 0; j < 8; j++) rq[j] = 1.0f / Rs[tx + 16 * j];
    float* Op = O + bofs + q0;
#pragma unroll
    for (int i = 0; i < 8; i++)
#pragma unroll
        for (int j = 0; j < 8; j++)
            Op[(long)(ty + 16 * i) * T_SZ + tx + 16 * j] = acc[i][j] * rq[j];
}

// ---------------------------------------------------------------------------
// Windowed branch (collapses to a mean) + Wo MLP -> out[..., 2048]
// ---------------------------------------------------------------------------
__global__ void __launch_bounds__(256) tail_kernel(
    const float* __restrict__ value,
    const float* __restrict__ Wo1, const float* __restrict__ bo1,
    const float* __restrict__ Wo2, const float* __restrict__ bo2,
    float* __restrict__ out)
{
    __shared__ float ex[128];
    __shared__ float hv[512];
    const int b = blockIdx.x;
    const int tid = threadIdx.x;
    const int w = tid >> 5, lane = tid & 31;

    // attn_ex[b][m] = mean(value[b][m][33:2047])  (2014 elements)
    for (int it = 0; it < 16; it++) {
        int m = it * 8 + w;
        const float* vp = value + ((long)b * M_SZ + m) * T_SZ;
        float s = 0.f;
        for (int k = 33 + lane; k < 2047; k += 32) s += vp[k];
#pragma unroll
        for (int o = 16; o; o >>= 1) s += __shfl_xor_sync(0xffffffffu, s, o);
        if (lane == 0) ex[m] = s * (1.0f / 2014.0f);
    }
    __syncthreads();

    for (int h = tid; h < 512; h += 256) {
        float s = bo1[h];
#pragma unroll 4
        for (int m = 0; m < 128; m++) s += Wo1[h * 128 + m] * ex[m];
        hv[h] = s;
    }
    __syncthreads();

    if (tid < 128) {
        float s = bo2[tid];
#pragma unroll 4
        for (int h = 0; h < 512; h++) s += Wo2[tid * 512 + h] * hv[h];
        s = s > 0.f ? s : 0.01f * s;
        out[((long)b * M_SZ + tid) * 2049 + 2048] = s;
    }
}

// ---------------------------------------------------------------------------
extern "C" void kernel_launch(void* const* d_in, const int* in_sizes, int n_in,
                              void* d_out, int out_size) {
    // metadata order: pattern, value, kernel_size, Wq1,bq1,Wq2,bq2, Wk1,bk1,Wk2,bk2, Wo1,bo1,Wo2,bo2
    const int ofs = (n_in >= 15) ? 3 : 2;  // tolerate scalar kernel_size missing
    const float* pattern = (const float*)d_in[0];
    const float* value   = (const float*)d_in[1];
    const float* Wq1 = (const float*)d_in[ofs + 0];
    const float* bq1 = (const float*)d_in[ofs + 1];
    const float* Wq2 = (const float*)d_in[ofs + 2];
    const float* bq2 = (const float*)d_in[ofs + 3];
    const float* Wk1 = (const float*)d_in[ofs + 4];
    const float* bk1 = (const float*)d_in[ofs + 5];
    const float* Wk2 = (const float*)d_in[ofs + 6];
    const float* bk2 = (const float*)d_in[ofs + 7];
    const float* Wo1 = (const float*)d_in[ofs + 8];
    const float* bo1 = (const float*)d_in[ofs + 9];
    const float* Wo2 = (const float*)d_in[ofs + 10];
    const float* bo2 = (const float*)d_in[ofs + 11];
    float* out = (float*)d_out;

    float *H, *Qb, *Kb, *Ab;
    cudaGetSymbolAddress((void**)&H,  g_H);
    cudaGetSymbolAddress((void**)&Qb, g_Q);
    cudaGetSymbolAddress((void**)&Kb, g_K);
    cudaGetSymbolAddress((void**)&Ab, g_A);

    cudaFuncSetAttribute(attn_main, cudaFuncAttributeMaxDynamicSharedMemorySize,
                         ATT_SMEM_BYTES);

    const dim3 blk(256);
    const dim3 g1(T_SZ / 128, H_SZ / 128, B_SZ);  // layer-1 GEMMs (512 x 2048)
    const dim3 g2(T_SZ / 128, M_SZ / 128, B_SZ);  // layer-2 GEMMs (128 x 2048)
    const long sP = (long)M_SZ * T_SZ;
    const long sH = (long)H_SZ * T_SZ;

    // query MLP
    sgemm_bias<0><<<g1, blk>>>(Wq1, pattern, bq1, H,  H_SZ, T_SZ, M_SZ, sP, sH, T_SZ);
    sgemm_bias<1><<<g2, blk>>>(Wq2, H,       bq2, Qb, M_SZ, T_SZ, H_SZ, sH, sP, T_SZ);
    // key MLP
    sgemm_bias<0><<<g1, blk>>>(Wk1, pattern, bk1, H,  H_SZ, T_SZ, M_SZ, sP, sH, T_SZ);
    sgemm_bias<1><<<g2, blk>>>(Wk2, H,       bk2, Kb, M_SZ, T_SZ, H_SZ, sH, sP, T_SZ);
    // full attention
    attn_main<<<dim3(T_SZ / 128, B_SZ), blk, ATT_SMEM_BYTES>>>(Qb, Kb, value, Ab);
    // output MLP -> out[..., 0:2048] (ldc = 2049)
    sgemm_bias<0><<<g1, blk>>>(Wo1, Ab, bo1, H,   H_SZ, T_SZ, M_SZ, sP, sH, T_SZ);
    sgemm_bias<1><<<g2, blk>>>(Wo2, H,  bo2, out, M_SZ, T_SZ, H_SZ, sH,
                               (long)M_SZ * 2049, 2049);
    // windowed branch (analytic mean) -> out[..., 2048]
    tail_kernel<<<B_SZ, 256>>>(value, Wo1, bo1, Wo2, bo2, out);
}

// round 4
// speedup vs baseline: 1.0017x; 1.0017x over previous
#include <cuda_runtime.h>

#define B_SZ 16
#define M_SZ 128
#define T_SZ 2048
#define H_SZ 512

// Scratch (device globals: allocation-free per harness rules)
__device__ float g_H[(size_t)B_SZ * H_SZ * T_SZ];   // 67 MB  hidden activations
__device__ float g_Q[(size_t)B_SZ * M_SZ * T_SZ];   // 16.8 MB
__device__ float g_K[(size_t)B_SZ * M_SZ * T_SZ];   // 16.8 MB
__device__ float g_A[(size_t)B_SZ * M_SZ * T_SZ];   // 16.8 MB attn_in

// ---------------------------------------------------------------------------
// Batched SGEMM: C[bz] = A (Md x K, shared) @ B[bz] (K x N) + bias, opt leaky
// 128x128 block tile, BK=8, 256 threads, 8x8 register tile.
// ---------------------------------------------------------------------------
template<int ACT>
__global__ void __launch_bounds__(256) sgemm_bias(
    const float* __restrict__ A, const float* __restrict__ B,
    const float* __restrict__ bias, float* __restrict__ C,
    int Md, int N, int K, long strideB, long strideC, int ldc)
{
    __shared__ float As[8][128];
    __shared__ float Bs[8][128];
    const int bz = blockIdx.z;
    const float* Bp = B + (long)bz * strideB;
    float* Cp = C + (long)bz * strideC;
    const int m0 = blockIdx.y * 128;
    const int n0 = blockIdx.x * 128;
    const int tid = threadIdx.x;
    const int tx = tid & 15;          // n-group
    const int ty = tid >> 4;          // m-group
    const int arow = tid >> 1, acol = (tid & 1) * 4;
    const int brow = tid >> 5, bcol = (tid & 31) * 4;

    float acc[8][8];
#pragma unroll
    for (int i = 0; i < 8; i++)
#pragma unroll
        for (int j = 0; j < 8; j++) acc[i][j] = 0.f;

    for (int k0 = 0; k0 < K; k0 += 8) {
        float4 av = *(const float4*)(A + (long)(m0 + arow) * K + k0 + acol);
        float4 bv = *(const float4*)(Bp + (long)(k0 + brow) * N + n0 + bcol);
        __syncthreads();
        As[acol + 0][arow] = av.x;
        As[acol + 1][arow] = av.y;
        As[acol + 2][arow] = av.z;
        As[acol + 3][arow] = av.w;
        *(float4*)(&Bs[brow][bcol]) = bv;
        __syncthreads();
#pragma unroll
        for (int kk = 0; kk < 8; kk++) {
            float4 a0 = *(const float4*)(&As[kk][ty * 8]);
            float4 a1 = *(const float4*)(&As[kk][ty * 8 + 4]);
            float4 b0 = *(const float4*)(&Bs[kk][tx * 8]);
            float4 b1 = *(const float4*)(&Bs[kk][tx * 8 + 4]);
            float ar[8] = {a0.x, a0.y, a0.z, a0.w, a1.x, a1.y, a1.z, a1.w};
            float br[8] = {b0.x, b0.y, b0.z, b0.w, b1.x, b1.y, b1.z, b1.w};
#pragma unroll
            for (int i = 0; i < 8; i++)
#pragma unroll
                for (int j = 0; j < 8; j++)
                    acc[i][j] += ar[i] * br[j];
        }
    }
#pragma unroll
    for (int i = 0; i < 8; i++) {
        int m = m0 + ty * 8 + i;
        float bb = bias[m];
#pragma unroll
        for (int j = 0; j < 8; j++) {
            float v = acc[i][j] + bb;
            if (ACT) v = v > 0.f ? v : 0.01f * v;
            Cp[(long)m * ldc + n0 + tx * 8 + j] = v;
        }
    }
}

// ---------------------------------------------------------------------------
// Fused attention, flash-style. Block = (q-tile of 128, batch).
// S[q,k] = sum_m Q[m,q] K[m,k]; w = exp(exp(S, diag-adjusted));
// out[m,q] = (sum_k w * V[m,k]) / (sum_k w).  No max needed: S std ~0.11.
// SMEM: Qs 128x128, Ks 128x64, Vs 128x65(pad), Ws 128x65(pad), Rs 128.
// ---------------------------------------------------------------------------
#define ATT_SMEM_FLOATS (128 * 128 + 128 * 64 + 128 * 65 + 128 * 65 + 128)
#define ATT_SMEM_BYTES (ATT_SMEM_FLOATS * 4)

__global__ void __launch_bounds__(256) attn_main(
    const float* __restrict__ Q, const float* __restrict__ Kb,
    const float* __restrict__ V, float* __restrict__ O)
{
    extern __shared__ float sm[];
    float* Qs = sm;                   // [m][128q]
    float* Ks = Qs + 128 * 128;       // [m][64k]
    float* Vs = Ks + 128 * 64;        // [m][65]
    float* Ws = Vs + 128 * 65;        // [q][65]
    float* Rs = Ws + 128 * 65;        // [128] running rowsum

    const int b = blockIdx.y;
    const int q0 = blockIdx.x * 128;
    const int tid = threadIdx.x;
    const int tx = tid & 15;
    const int ty = tid >> 4;
    const long bofs = (long)b * M_SZ * T_SZ;
    const float* Qp = Q + bofs + q0;

    for (int i = tid * 4; i < 128 * 128; i += 1024) {
        int m = i >> 7, q = i & 127;
        *(float4*)(Qs + i) = *(const float4*)(Qp + (long)m * T_SZ + q);
    }
    if (tid < 128) Rs[tid] = 0.f;

    float acc[8][8];
#pragma unroll
    for (int i = 0; i < 8; i++)
#pragma unroll
        for (int j = 0; j < 8; j++) acc[i][j] = 0.f;

    const float cdiag = 0.97790291308792045f;  // 1 - 1/sqrt(2048)

    for (int kt = 0; kt < 32; kt++) {
        const int kbase = kt * 64;
        __syncthreads();  // previous readers of Ks/Vs/Ws done (also orders Q load)
        const float* Kp = Kb + bofs + kbase;
        const float* Vp = V + bofs + kbase;
        for (int i = tid * 4; i < 128 * 64; i += 1024) {
            int m = i >> 6, k = i & 63;
            *(float4*)(Ks + m * 64 + k) = *(const float4*)(Kp + (long)m * T_SZ + k);
            float4 vv = *(const float4*)(Vp + (long)m * T_SZ + k);
            Vs[m * 65 + k] = vv.x;
            Vs[m * 65 + k + 1] = vv.y;
            Vs[m * 65 + k + 2] = vv.z;
            Vs[m * 65 + k + 3] = vv.w;
        }
        __syncthreads();

        // S phase: thread covers q = tx + 16i (i<8), k = ty + 16j (j<4)
        float s[8][4];
#pragma unroll
        for (int i = 0; i < 8; i++)
#pragma unroll
            for (int j = 0; j < 4; j++) s[i][j] = 0.f;

#pragma unroll 4
        for (int m = 0; m < 128; m++) {
            float qr[8], kr[4];
#pragma unroll
            for (int i = 0; i < 8; i++) qr[i] = Qs[m * 128 + tx + 16 * i];
#pragma unroll
            for (int j = 0; j < 4; j++) kr[j] = Ks[m * 64 + ty + 16 * j];
#pragma unroll
            for (int i = 0; i < 8; i++)
#pragma unroll
                for (int j = 0; j < 4; j++)
                    s[i][j] += qr[i] * kr[j];
        }
#pragma unroll
        for (int i = 0; i < 8; i++) {
            int gq = q0 + tx + 16 * i;
#pragma unroll
            for (int j = 0; j < 4; j++) {
                int gk = kbase + ty + 16 * j;
                float x = s[i][j];
                if (gq == gk) x *= cdiag;
                Ws[(tx + 16 * i) * 65 + ty + 16 * j] = expf(expf(x));
            }
        }
        __syncthreads();

        // rowsum accumulation (threads 0..127, conflict-free column walk)
        if (tid < 128) {
            float r = 0.f;
#pragma unroll
            for (int k = 0; k < 64; k++) r += Ws[tid * 65 + k];
            Rs[tid] += r;
        }

        // AV phase: thread covers m = ty + 16i (i<8), q = tx + 16j (j<8)
#pragma unroll 4
        for (int k = 0; k < 64; k++) {
            float vr[8], wr[8];
#pragma unroll
            for (int i = 0; i < 8; i++) vr[i] = Vs[(ty + 16 * i) * 65 + k];
#pragma unroll
            for (int j = 0; j < 8; j++) wr[j] = Ws[(tx + 16 * j) * 65 + k];
#pragma unroll
            for (int i = 0; i < 8; i++)
#pragma unroll
                for (int j = 0; j < 8; j++)
                    acc[i][j] += vr[i] * wr[j];
        }
    }
    __syncthreads();  // Rs final

    float rq[8];
#pragma unroll
    for (int j = 0; j < 8; j++) rq[j] = 1.0f / Rs[tx + 16 * j];
    float* Op = O + bofs + q0;
#pragma unroll
    for (int i = 0; i < 8; i++)
#pragma unroll
        for (int j = 0; j < 8; j++)
            Op[(long)(ty + 16 * i) * T_SZ + tx + 16 * j] = acc[i][j] * rq[j];
}

// ---------------------------------------------------------------------------
// Windowed branch (collapses to a mean) + Wo MLP -> out[..., 2048]
// ---------------------------------------------------------------------------
__global__ void __launch_bounds__(256) tail_kernel(
    const float* __restrict__ value,
    const float* __restrict__ Wo1, const float* __restrict__ bo1,
    const float* __restrict__ Wo2, const float* __restrict__ bo2,
    float* __restrict__ out)
{
    __shared__ float ex[128];
    __shared__ float hv[512];
    const int b = blockIdx.x;
    const int tid = threadIdx.x;
    const int w = tid >> 5, lane = tid & 31;

    // attn_ex[b][m] = mean(value[b][m][33:2047])  (2014 elements)
    for (int it = 0; it < 16; it++) {
        int m = it * 8 + w;
        const float* vp = value + ((long)b * M_SZ + m) * T_SZ;
        float s = 0.f;
        for (int k = 33 + lane; k < 2047; k += 32) s += vp[k];
#pragma unroll
        for (int o = 16; o; o >>= 1) s += __shfl_xor_sync(0xffffffffu, s, o);
        if (lane == 0) ex[m] = s * (1.0f / 2014.0f);
    }
    __syncthreads();

    for (int h = tid; h < 512; h += 256) {
        float s = bo1[h];
#pragma unroll 4
        for (int m = 0; m < 128; m++) s += Wo1[h * 128 + m] * ex[m];
        hv[h] = s;
    }
    __syncthreads();

    if (tid < 128) {
        float s = bo2[tid];
#pragma unroll 4
        for (int h = 0; h < 512; h++) s += Wo2[tid * 512 + h] * hv[h];
        s = s > 0.f ? s : 0.01f * s;
        out[((long)b * M_SZ + tid) * 2049 + 2048] = s;
    }
}

// ---------------------------------------------------------------------------
extern "C" void kernel_launch(void* const* d_in, const int* in_sizes, int n_in,
                              void* d_out, int out_size) {
    // metadata order: pattern, value, kernel_size, Wq1,bq1,Wq2,bq2, Wk1,bk1,Wk2,bk2, Wo1,bo1,Wo2,bo2
    const int ofs = (n_in >= 15) ? 3 : 2;  // tolerate scalar kernel_size missing
    const float* pattern = (const float*)d_in[0];
    const float* value   = (const float*)d_in[1];
    const float* Wq1 = (const float*)d_in[ofs + 0];
    const float* bq1 = (const float*)d_in[ofs + 1];
    const float* Wq2 = (const float*)d_in[ofs + 2];
    const float* bq2 = (const float*)d_in[ofs + 3];
    const float* Wk1 = (const float*)d_in[ofs + 4];
    const float* bk1 = (const float*)d_in[ofs + 5];
    const float* Wk2 = (const float*)d_in[ofs + 6];
    const float* bk2 = (const float*)d_in[ofs + 7];
    const float* Wo1 = (const float*)d_in[ofs + 8];
    const float* bo1 = (const float*)d_in[ofs + 9];
    const float* Wo2 = (const float*)d_in[ofs + 10];
    const float* bo2 = (const float*)d_in[ofs + 11];
    float* out = (float*)d_out;

    float *H, *Qb, *Kb, *Ab;
    cudaGetSymbolAddress((void**)&H,  g_H);
    cudaGetSymbolAddress((void**)&Qb, g_Q);
    cudaGetSymbolAddress((void**)&Kb, g_K);
    cudaGetSymbolAddress((void**)&Ab, g_A);

    cudaFuncSetAttribute(attn_main, cudaFuncAttributeMaxDynamicSharedMemorySize,
                         ATT_SMEM_BYTES);

    const dim3 blk(256);
    const dim3 g1(T_SZ / 128, H_SZ / 128, B_SZ);  // layer-1 GEMMs (512 x 2048)
    const dim3 g2(T_SZ / 128, M_SZ / 128, B_SZ);  // layer-2 GEMMs (128 x 2048)
    const long sP = (long)M_SZ * T_SZ;
    const long sH = (long)H_SZ * T_SZ;

    // query MLP
    sgemm_bias<0><<<g1, blk>>>(Wq1, pattern, bq1, H,  H_SZ, T_SZ, M_SZ, sP, sH, T_SZ);
    sgemm_bias<1><<<g2, blk>>>(Wq2, H,       bq2, Qb, M_SZ, T_SZ, H_SZ, sH, sP, T_SZ);
    // key MLP
    sgemm_bias<0><<<g1, blk>>>(Wk1, pattern, bk1, H,  H_SZ, T_SZ, M_SZ, sP, sH, T_SZ);
    sgemm_bias<1><<<g2, blk>>>(Wk2, H,       bk2, Kb, M_SZ, T_SZ, H_SZ, sH, sP, T_SZ);
    // full attention
    attn_main<<<dim3(T_SZ / 128, B_SZ), blk, ATT_SMEM_BYTES>>>(Qb, Kb, value, Ab);
    // output MLP -> out[..., 0:2048] (ldc = 2049)
    sgemm_bias<0><<<g1, blk>>>(Wo1, Ab, bo1, H,   H_SZ, T_SZ, M_SZ, sP, sH, T_SZ);
    sgemm_bias<1><<<g2, blk>>>(Wo2, H,  bo2, out, M_SZ, T_SZ, H_SZ, sH,
                               (long)M_SZ * 2049, 2049);
    // windowed branch (analytic mean) -> out[..., 2048]
    tail_kernel<<<B_SZ, 256>>>(value, Wo1, bo1, Wo2, bo2, out);
}

// round 7
// speedup vs baseline: 2.4237x; 2.4196x over previous
#include <cuda_runtime.h>
#include <cuda_bf16.h>
#include <cstdint>

typedef __nv_bfloat16  bf16;
typedef __nv_bfloat162 bf162;

#define B_SZ 16
#define M_SZ 128
#define T_SZ 2048
#define H_SZ 512

// ---------------------------------------------------------------------------
// Scratch (device globals, allocation-free). All fp32, token-major.
// ---------------------------------------------------------------------------
__device__ float g_P[(size_t)B_SZ * T_SZ * M_SZ];   // pattern, [b][t][m]
__device__ float g_H[(size_t)B_SZ * T_SZ * H_SZ];   // hidden,  [b][t][h]
__device__ float g_Q[(size_t)B_SZ * T_SZ * M_SZ];   // query,   [b][t][m]
__device__ float g_K[(size_t)B_SZ * T_SZ * M_SZ];   // key,     [b][t][m]
__device__ float g_A[(size_t)B_SZ * T_SZ * M_SZ];   // attn out,[b][t][m]

// ---------------------------------------------------------------------------
// HMMA m16n8k16 bf16 (plain PTX, works on non-'a' target)
// Thread map (lane g = lane>>2, t = lane&3):
//  A frag a0..a3: rows g / g+8, k cols t*2,t*2+1 / +8
//  B frag b0,b1 : n = g, k = t*2,t*2+1 / +8   (B stored [n][k], k contiguous)
//  D d0..d3     : rows g / g+8, cols t*2, t*2+1
// ---------------------------------------------------------------------------
__device__ __forceinline__ void mma16816(float* d, const uint32_t* a,
                                         const uint32_t* b) {
    asm volatile(
        "mma.sync.aligned.m16n8k16.row.col.f32.bf16.bf16.f32 "
        "{%0,%1,%2,%3}, {%4,%5,%6,%7}, {%8,%9}, {%0,%1,%2,%3};\n"
        : "+f"(d[0]), "+f"(d[1]), "+f"(d[2]), "+f"(d[3])
        : "r"(a[0]), "r"(a[1]), "r"(a[2]), "r"(a[3]), "r"(b[0]), "r"(b[1]));
}

__device__ __forceinline__ void split2(float v, bf16& h, bf16& l) {
    h = __float2bfloat16(v);
    l = __float2bfloat16(v - __bfloat162float(h));
}

// ---------------------------------------------------------------------------
// Transpose: pattern [b][m][t] fp32 -> g_P [b][t][m] fp32
// ---------------------------------------------------------------------------
__global__ void __launch_bounds__(256) conv_T(const float* __restrict__ p,
                                              float* __restrict__ o) {
    __shared__ float s[32][33];
    const int b = blockIdx.z, t0 = blockIdx.x * 32, m0 = blockIdx.y * 32;
    const int tid = threadIdx.x;
#pragma unroll
    for (int u = 0; u < 4; u++) {
        int lin = tid + u * 256;
        int mm = lin >> 5, tt = lin & 31;
        s[mm][tt] = p[((long)b * M_SZ + m0 + mm) * T_SZ + t0 + tt];
    }
    __syncthreads();
#pragma unroll
    for (int u = 0; u < 4; u++) {
        int lin = tid + u * 256;
        int tt = lin >> 5, mm = lin & 31;
        o[((long)b * T_SZ + t0 + tt) * M_SZ + m0 + mm] = s[mm][tt];
    }
}

// ---------------------------------------------------------------------------
// Generic NT GEMM (bf16x3 HMMA): D[i][j] = sum_k A[i][k]*W[j][k] + bias[j]
// A fp32 batch-strided, W fp32 shared across batch. 256 thr, tile 128x128, BK=32.
// MODE1=0: Y fp32 token-major Y[b*strideY + i*F + j]
// MODE1=1: Y fp32 strided     Y[(b*128 + j)*2049 + i]
// ---------------------------------------------------------------------------
#define LDA 40   // 32 + 8 pad (halves); row stride 80B -> conflict-free frags

template<int ACT, int MODE1>
__global__ void __launch_bounds__(256, 1) gemm_nt(
    const float* __restrict__ A, const float* __restrict__ W,
    const float* __restrict__ bias, float* __restrict__ Y,
    int K, long strideA, long strideY)
{
    __shared__ bf16 Ah[128 * LDA], Al[128 * LDA];
    __shared__ bf16 Bh[128 * LDA], Bl[128 * LDA];
    __shared__ float sbias[128];
    const int tid = threadIdx.x, lane = tid & 31, wid = tid >> 5;
    const int gID = lane >> 2, thID = lane & 3;
    const int b = blockIdx.z, i0 = blockIdx.x * 128, j0 = blockIdx.y * 128;
    const int F = gridDim.y * 128;
    const int wM = (wid >> 1) * 32, wN = (wid & 1) * 64;

    if (tid < 128) sbias[tid] = bias[j0 + tid];

    float acc[2][8][4];
#pragma unroll
    for (int mt = 0; mt < 2; mt++)
#pragma unroll
        for (int nt = 0; nt < 8; nt++)
#pragma unroll
            for (int e = 0; e < 4; e++) acc[mt][nt][e] = 0.f;

    const float* Ap = A + (long)b * strideA + (long)i0 * K;
    const float* Wp = W + (long)j0 * K;

    for (int k0 = 0; k0 < K; k0 += 32) {
        __syncthreads();
#pragma unroll
        for (int u = 0; u < 4; u++) {
            int lin = tid + u * 256;
            int r = lin >> 3, c4 = (lin & 7) * 4;
            float4 av = *(const float4*)(Ap + (long)r * K + k0 + c4);
            bf162 h0, l0, h1, l1;
            split2(av.x, h0.x, l0.x); split2(av.y, h0.y, l0.y);
            split2(av.z, h1.x, l1.x); split2(av.w, h1.y, l1.y);
            *(bf162*)&Ah[r * LDA + c4]     = h0;
            *(bf162*)&Ah[r * LDA + c4 + 2] = h1;
            *(bf162*)&Al[r * LDA + c4]     = l0;
            *(bf162*)&Al[r * LDA + c4 + 2] = l1;
            float4 bv = *(const float4*)(Wp + (long)r * K + k0 + c4);
            split2(bv.x, h0.x, l0.x); split2(bv.y, h0.y, l0.y);
            split2(bv.z, h1.x, l1.x); split2(bv.w, h1.y, l1.y);
            *(bf162*)&Bh[r * LDA + c4]     = h0;
            *(bf162*)&Bh[r * LDA + c4 + 2] = h1;
            *(bf162*)&Bl[r * LDA + c4]     = l0;
            *(bf162*)&Bl[r * LDA + c4 + 2] = l1;
        }
        __syncthreads();
#pragma unroll
        for (int ks = 0; ks < 2; ks++) {
            const int kb = ks * 16 + thID * 2;
            uint32_t ah[2][4], al[2][4], bh[8][2], bl[8][2];
#pragma unroll
            for (int mt = 0; mt < 2; mt++) {
                int r = wM + mt * 16 + gID;
                ah[mt][0] = *(const uint32_t*)&Ah[r * LDA + kb];
                ah[mt][1] = *(const uint32_t*)&Ah[(r + 8) * LDA + kb];
                ah[mt][2] = *(const uint32_t*)&Ah[r * LDA + kb + 8];
                ah[mt][3] = *(const uint32_t*)&Ah[(r + 8) * LDA + kb + 8];
                al[mt][0] = *(const uint32_t*)&Al[r * LDA + kb];
                al[mt][1] = *(const uint32_t*)&Al[(r + 8) * LDA + kb];
                al[mt][2] = *(const uint32_t*)&Al[r * LDA + kb + 8];
                al[mt][3] = *(const uint32_t*)&Al[(r + 8) * LDA + kb + 8];
            }
#pragma unroll
            for (int nt = 0; nt < 8; nt++) {
                int rn = wN + nt * 8 + gID;
                bh[nt][0] = *(const uint32_t*)&Bh[rn * LDA + kb];
                bh[nt][1] = *(const uint32_t*)&Bh[rn * LDA + kb + 8];
                bl[nt][0] = *(const uint32_t*)&Bl[rn * LDA + kb];
                bl[nt][1] = *(const uint32_t*)&Bl[rn * LDA + kb + 8];
            }
#pragma unroll
            for (int mt = 0; mt < 2; mt++)
#pragma unroll
                for (int nt = 0; nt < 8; nt++) {
                    mma16816(acc[mt][nt], ah[mt], bh[nt]);
                    mma16816(acc[mt][nt], ah[mt], bl[nt]);
                    mma16816(acc[mt][nt], al[mt], bh[nt]);
                }
        }
    }

    // epilogue
#pragma unroll
    for (int mt = 0; mt < 2; mt++)
#pragma unroll
        for (int nt = 0; nt < 8; nt++) {
            int i_ = wM + mt * 16 + gID;
            int j_ = wN + nt * 8 + thID * 2;
            float v0 = acc[mt][nt][0] + sbias[j_];
            float v1 = acc[mt][nt][1] + sbias[j_ + 1];
            float v2 = acc[mt][nt][2] + sbias[j_];
            float v3 = acc[mt][nt][3] + sbias[j_ + 1];
            if (ACT) {
                v0 = v0 > 0.f ? v0 : 0.01f * v0;
                v1 = v1 > 0.f ? v1 : 0.01f * v1;
                v2 = v2 > 0.f ? v2 : 0.01f * v2;
                v3 = v3 > 0.f ? v3 : 0.01f * v3;
            }
            if (!MODE1) {
                float* yp = Y + (long)b * strideY + (long)(i0 + i_) * F + j0 + j_;
                float2 p0 = {v0, v1}, p1 = {v2, v3};
                *(float2*)yp = p0;
                *(float2*)(yp + 8L * F) = p1;
            } else {
                long c0 = ((long)b * 128 + j0 + j_) * 2049 + i0 + i_;
                Y[c0] = v0;
                Y[c0 + 2049] = v1;
                Y[c0 + 8] = v2;
                Y[c0 + 2049 + 8] = v3;
            }
        }
}

// ---------------------------------------------------------------------------
// Fused attention (bf16x3 HMMA). CTA = (q-tile 128, batch), 256 threads.
//   S[q][k] = sum_m Q[q][m] K[k][m];  w = exp(exp(S diag-adj))
//   AV[q][m] += sum_k w[q][k] V[m][k];  out = AV / rowsum
// ---------------------------------------------------------------------------
#define LDW 136   // 128 + 8 pad (halves); 272B row stride -> conflict-free
#define TILE_HALF (128 * LDW)            // halves per buffer
#define ATT_SMEM (6 * TILE_HALF * 2 + 2 * 128 * 4 + 128 * 4)

__global__ void __launch_bounds__(256, 1) attn_hmma(
    const float* __restrict__ Q, const float* __restrict__ Kb,
    const float* __restrict__ V, float* __restrict__ O)
{
    extern __shared__ __align__(16) char smem[];
    bf16* Qh  = (bf16*)smem;
    bf16* Ql  = Qh + TILE_HALF;
    bf16* KVh = Ql + TILE_HALF;
    bf16* KVl = KVh + TILE_HALF;
    bf16* Wh  = KVl + TILE_HALF;
    bf16* Wl  = Wh + TILE_HALF;
    float* rsP    = (float*)(Wl + TILE_HALF);   // [2][128]
    float* srecip = rsP + 256;                  // [128]

    const int tid = threadIdx.x, lane = tid & 31, wid = tid >> 5;
    const int gID = lane >> 2, thID = lane & 3;
    const int b = blockIdx.y, q0 = blockIdx.x * 128;
    const int wM = (wid >> 1) * 32, wN = (wid & 1) * 64;
    const float cdiag = 0.97790291308792045f;   // 1 - 1/sqrt(2048)

    // load Q tile (fp32 -> hi/lo split)
    {
        const float* src = Q + ((long)b * T_SZ + q0) * M_SZ;
#pragma unroll
        for (int u = 0; u < 16; u++) {
            int lin = tid + u * 256;
            int r = lin >> 5, c4 = (lin & 31) * 4;
            float4 v = *(const float4*)(src + (long)r * M_SZ + c4);
            bf162 h0, l0, h1, l1;
            split2(v.x, h0.x, l0.x); split2(v.y, h0.y, l0.y);
            split2(v.z, h1.x, l1.x); split2(v.w, h1.y, l1.y);
            *(bf162*)&Qh[r * LDW + c4]     = h0;
            *(bf162*)&Qh[r * LDW + c4 + 2] = h1;
            *(bf162*)&Ql[r * LDW + c4]     = l0;
            *(bf162*)&Ql[r * LDW + c4 + 2] = l1;
        }
    }
    if (tid < 256) rsP[tid] = 0.f;

    float accv[2][8][4];
#pragma unroll
    for (int mt = 0; mt < 2; mt++)
#pragma unroll
        for (int nt = 0; nt < 8; nt++)
#pragma unroll
            for (int e = 0; e < 4; e++) accv[mt][nt][e] = 0.f;

    for (int kt = 0; kt < 16; kt++) {
        __syncthreads();   // prior AV done reading KV/W; Q/rsP visible on kt=0
        // K tile: rows = key index, cols = m
        {
            const float* src = Kb + ((long)b * T_SZ + kt * 128) * M_SZ;
#pragma unroll
            for (int u = 0; u < 16; u++) {
                int lin = tid + u * 256;
                int r = lin >> 5, c4 = (lin & 31) * 4;
                float4 v = *(const float4*)(src + (long)r * M_SZ + c4);
                bf162 h0, l0, h1, l1;
                split2(v.x, h0.x, l0.x); split2(v.y, h0.y, l0.y);
                split2(v.z, h1.x, l1.x); split2(v.w, h1.y, l1.y);
                *(bf162*)&KVh[r * LDW + c4]     = h0;
                *(bf162*)&KVh[r * LDW + c4 + 2] = h1;
                *(bf162*)&KVl[r * LDW + c4]     = l0;
                *(bf162*)&KVl[r * LDW + c4 + 2] = l1;
            }
        }
        __syncthreads();

        // S = Q K^T  (k-dim = m, 8 steps of 16)
        float accs[2][8][4];
#pragma unroll
        for (int mt = 0; mt < 2; mt++)
#pragma unroll
            for (int nt = 0; nt < 8; nt++)
#pragma unroll
                for (int e = 0; e < 4; e++) accs[mt][nt][e] = 0.f;
#pragma unroll
        for (int ks = 0; ks < 8; ks++) {
            const int kb = ks * 16 + thID * 2;
            uint32_t ah[2][4], al[2][4], bh[8][2], bl[8][2];
#pragma unroll
            for (int mt = 0; mt < 2; mt++) {
                int r = wM + mt * 16 + gID;
                ah[mt][0] = *(const uint32_t*)&Qh[r * LDW + kb];
                ah[mt][1] = *(const uint32_t*)&Qh[(r + 8) * LDW + kb];
                ah[mt][2] = *(const uint32_t*)&Qh[r * LDW + kb + 8];
                ah[mt][3] = *(const uint32_t*)&Qh[(r + 8) * LDW + kb + 8];
                al[mt][0] = *(const uint32_t*)&Ql[r * LDW + kb];
                al[mt][1] = *(const uint32_t*)&Ql[(r + 8) * LDW + kb];
                al[mt][2] = *(const uint32_t*)&Ql[r * LDW + kb + 8];
                al[mt][3] = *(const uint32_t*)&Ql[(r + 8) * LDW + kb + 8];
            }
#pragma unroll
            for (int nt = 0; nt < 8; nt++) {
                int rn = wN + nt * 8 + gID;
                bh[nt][0] = *(const uint32_t*)&KVh[rn * LDW + kb];
                bh[nt][1] = *(const uint32_t*)&KVh[rn * LDW + kb + 8];
                bl[nt][0] = *(const uint32_t*)&KVl[rn * LDW + kb];
                bl[nt][1] = *(const uint32_t*)&KVl[rn * LDW + kb + 8];
            }
#pragma unroll
            for (int mt = 0; mt < 2; mt++)
#pragma unroll
                for (int nt = 0; nt < 8; nt++) {
                    mma16816(accs[mt][nt], ah[mt], bh[nt]);
                    mma16816(accs[mt][nt], ah[mt], bl[nt]);
                    mma16816(accs[mt][nt], al[mt], bh[nt]);
                }
        }

        // w = exp(exp(S)), rowsum partials, split -> W smem
        float rp[2][2] = {{0.f, 0.f}, {0.f, 0.f}};
#pragma unroll
        for (int mt = 0; mt < 2; mt++)
#pragma unroll
            for (int nt = 0; nt < 8; nt++) {
                int ql = wM + mt * 16 + gID;
                int kl = wN + nt * 8 + thID * 2;
                int qi = q0 + ql, kk = kt * 128 + kl;
                float x0 = accs[mt][nt][0], x1 = accs[mt][nt][1];
                float x2 = accs[mt][nt][2], x3 = accs[mt][nt][3];
                if (qi == kk)         x0 *= cdiag;
                if (qi == kk + 1)     x1 *= cdiag;
                if (qi + 8 == kk)     x2 *= cdiag;
                if (qi + 8 == kk + 1) x3 *= cdiag;
                float w0 = __expf(__expf(x0));
                float w1 = __expf(__expf(x1));
                float w2 = __expf(__expf(x2));
                float w3 = __expf(__expf(x3));
                rp[mt][0] += w0 + w1;
                rp[mt][1] += w2 + w3;
                bf162 h0, l0, h1, l1;
                split2(w0, h0.x, l0.x); split2(w1, h0.y, l0.y);
                split2(w2, h1.x, l1.x); split2(w3, h1.y, l1.y);
                *(bf162*)&Wh[ql * LDW + kl]       = h0;
                *(bf162*)&Wl[ql * LDW + kl]       = l0;
                *(bf162*)&Wh[(ql + 8) * LDW + kl] = h1;
                *(bf162*)&Wl[(ql + 8) * LDW + kl] = l1;
            }
        // deterministic rowsum: reduce over thID group, one writer per row
#pragma unroll
        for (int mt = 0; mt < 2; mt++)
#pragma unroll
            for (int h = 0; h < 2; h++) {
                float s = rp[mt][h];
                s += __shfl_xor_sync(0xffffffffu, s, 1);
                s += __shfl_xor_sync(0xffffffffu, s, 2);
                if (thID == 0)
                    rsP[(wid & 1) * 128 + wM + mt * 16 + gID + h * 8] += s;
            }
        __syncthreads();   // S reads of KV done; W writes done

        // V tile: rows = m (feature), cols = time k (contiguous in value)
        {
            const float* src = V + (long)b * M_SZ * T_SZ + kt * 128;
#pragma unroll
            for (int u = 0; u < 16; u++) {
                int lin = tid + u * 256;
                int r = lin >> 5, c4 = (lin & 31) * 4;
                float4 v = *(const float4*)(src + (long)r * T_SZ + c4);
                bf162 h0, l0, h1, l1;
                split2(v.x, h0.x, l0.x); split2(v.y, h0.y, l0.y);
                split2(v.z, h1.x, l1.x); split2(v.w, h1.y, l1.y);
                *(bf162*)&KVh[r * LDW + c4]     = h0;
                *(bf162*)&KVh[r * LDW + c4 + 2] = h1;
                *(bf162*)&KVl[r * LDW + c4]     = l0;
                *(bf162*)&KVl[r * LDW + c4 + 2] = l1;
            }
        }
        __syncthreads();

        // AV += W V^T  (k-dim = time, 8 steps of 16)
#pragma unroll
        for (int ks = 0; ks < 8; ks++) {
            const int kb = ks * 16 + thID * 2;
            uint32_t ah[2][4], al[2][4], bh[8][2], bl[8][2];
#pragma unroll
            for (int mt = 0; mt < 2; mt++) {
                int r = wM + mt * 16 + gID;
                ah[mt][0] = *(const uint32_t*)&Wh[r * LDW + kb];
                ah[mt][1] = *(const uint32_t*)&Wh[(r + 8) * LDW + kb];
                ah[mt][2] = *(const uint32_t*)&Wh[r * LDW + kb + 8];
                ah[mt][3] = *(const uint32_t*)&Wh[(r + 8) * LDW + kb + 8];
                al[mt][0] = *(const uint32_t*)&Wl[r * LDW + kb];
                al[mt][1] = *(const uint32_t*)&Wl[(r + 8) * LDW + kb];
                al[mt][2] = *(const uint32_t*)&Wl[r * LDW + kb + 8];
                al[mt][3] = *(const uint32_t*)&Wl[(r + 8) * LDW + kb + 8];
            }
#pragma unroll
            for (int nt = 0; nt < 8; nt++) {
                int rn = wN + nt * 8 + gID;
                bh[nt][0] = *(const uint32_t*)&KVh[rn * LDW + kb];
                bh[nt][1] = *(const uint32_t*)&KVh[rn * LDW + kb + 8];
                bl[nt][0] = *(const uint32_t*)&KVl[rn * LDW + kb];
                bl[nt][1] = *(const uint32_t*)&KVl[rn * LDW + kb + 8];
            }
#pragma unroll
            for (int mt = 0; mt < 2; mt++)
#pragma unroll
                for (int nt = 0; nt < 8; nt++) {
                    mma16816(accv[mt][nt], ah[mt], bh[nt]);
                    mma16816(accv[mt][nt], ah[mt], bl[nt]);
                    mma16816(accv[mt][nt], al[mt], bh[nt]);
                }
        }
    }
    __syncthreads();
    if (tid < 128) srecip[tid] = 1.0f / (rsP[tid] + rsP[128 + tid]);
    __syncthreads();

    // out[b][q][m] = AV[q][m] / rowsum[q]
#pragma unroll
    for (int mt = 0; mt < 2; mt++)
#pragma unroll
        for (int nt = 0; nt < 8; nt++) {
            int i_ = wM + mt * 16 + gID;
            int j_ = wN + nt * 8 + thID * 2;
            float r0 = srecip[i_], r1 = srecip[i_ + 8];
            float2 p0 = {accv[mt][nt][0] * r0, accv[mt][nt][1] * r0};
            float2 p1 = {accv[mt][nt][2] * r1, accv[mt][nt][3] * r1};
            float* op = O + ((long)b * T_SZ + q0 + i_) * M_SZ + j_;
            *(float2*)op = p0;
            *(float2*)(op + 8L * M_SZ) = p1;
        }
}

// ---------------------------------------------------------------------------
// Windowed branch (Tq=1 => uniform softmax => mean of value[...,33:2047]) + Wo
// ---------------------------------------------------------------------------
__global__ void __launch_bounds__(256) tail_kernel(
    const float* __restrict__ value,
    const float* __restrict__ Wo1, const float* __restrict__ bo1,
    const float* __restrict__ Wo2, const float* __restrict__ bo2,
    float* __restrict__ out)
{
    __shared__ float ex[128];
    __shared__ float hv[512];
    const int b = blockIdx.x, tid = threadIdx.x;
    const int w = tid >> 5, lane = tid & 31;

    for (int it = 0; it < 16; it++) {
        int m = it * 8 + w;
        const float* vp = value + ((long)b * M_SZ + m) * T_SZ;
        float s = 0.f;
        for (int k = 33 + lane; k < 2047; k += 32) s += vp[k];
#pragma unroll
        for (int o = 16; o; o >>= 1) s += __shfl_xor_sync(0xffffffffu, s, o);
        if (lane == 0) ex[m] = s * (1.0f / 2014.0f);
    }
    __syncthreads();
    for (int h = tid; h < 512; h += 256) {
        float s = bo1[h];
#pragma unroll 4
        for (int m = 0; m < 128; m++) s += Wo1[h * 128 + m] * ex[m];
        hv[h] = s;
    }
    __syncthreads();
    if (tid < 128) {
        float s = bo2[tid];
#pragma unroll 4
        for (int h = 0; h < 512; h++) s += Wo2[tid * 512 + h] * hv[h];
        s = s > 0.f ? s : 0.01f * s;
        out[((long)b * M_SZ + tid) * 2049 + 2048] = s;
    }
}

// ---------------------------------------------------------------------------
extern "C" void kernel_launch(void* const* d_in, const int* in_sizes, int n_in,
                              void* d_out, int out_size) {
    const int ofs = (n_in >= 15) ? 3 : 2;
    const float* pattern = (const float*)d_in[0];
    const float* value   = (const float*)d_in[1];
    const float* Wq1 = (const float*)d_in[ofs + 0];
    const float* bq1 = (const float*)d_in[ofs + 1];
    const float* Wq2 = (const float*)d_in[ofs + 2];
    const float* bq2 = (const float*)d_in[ofs + 3];
    const float* Wk1 = (const float*)d_in[ofs + 4];
    const float* bk1 = (const float*)d_in[ofs + 5];
    const float* Wk2 = (const float*)d_in[ofs + 6];
    const float* bk2 = (const float*)d_in[ofs + 7];
    const float* Wo1 = (const float*)d_in[ofs + 8];
    const float* bo1 = (const float*)d_in[ofs + 9];
    const float* Wo2 = (const float*)d_in[ofs + 10];
    const float* bo2 = (const float*)d_in[ofs + 11];
    float* out = (float*)d_out;

    float *P, *H, *Qb, *Kb, *Ab;
    cudaGetSymbolAddress((void**)&P,  g_P);
    cudaGetSymbolAddress((void**)&H,  g_H);
    cudaGetSymbolAddress((void**)&Qb, g_Q);
    cudaGetSymbolAddress((void**)&Kb, g_K);
    cudaGetSymbolAddress((void**)&Ab, g_A);

    cudaFuncSetAttribute(attn_hmma, cudaFuncAttributeMaxDynamicSharedMemorySize,
                         ATT_SMEM);

    const long sPM = (long)T_SZ * M_SZ;   // activation batch strides
    const long sPH = (long)T_SZ * H_SZ;

    conv_T<<<dim3(64, 4, 16), 256>>>(pattern, P);

    const dim3 g1(16, 4, 16);   // layer-1: F = 512
    const dim3 g2(16, 1, 16);   // layer-2: F = 128

    // query MLP
    gemm_nt<0,0><<<g1, 256>>>(P, Wq1, bq1, H,  128, sPM, sPH);
    gemm_nt<1,0><<<g2, 256>>>(H, Wq2, bq2, Qb, 512, sPH, sPM);
    // key MLP
    gemm_nt<0,0><<<g1, 256>>>(P, Wk1, bk1, H,  128, sPM, sPH);
    gemm_nt<1,0><<<g2, 256>>>(H, Wk2, bk2, Kb, 512, sPH, sPM);
    // attention
    attn_hmma<<<dim3(16, 16), 256, ATT_SMEM>>>(Qb, Kb, value, Ab);
    // output MLP -> out[..., 0:2048]
    gemm_nt<0,0><<<g1, 256>>>(Ab, Wo1, bo1, H,  128, sPM, sPH);
    gemm_nt<1,1><<<g2, 256>>>(H, Wo2, bo2, out, 512, sPH, 0);
    // windowed branch -> out[..., 2048]
    tail_kernel<<<B_SZ, 256>>>(value, Wo1, bo1, Wo2, bo2, out);
}

// round 8
// speedup vs baseline: 2.4869x; 1.0261x over previous
#include <cuda_runtime.h>
#include <cuda_bf16.h>
#include <cstdint>

typedef __nv_bfloat16  bf16;
typedef __nv_bfloat162 bf162;

#define B_SZ 16
#define M_SZ 128
#define T_SZ 2048
#define H_SZ 512

// ---------------------------------------------------------------------------
// Scratch (device globals, allocation-free). Separate bf16 hi/lo planes.
// ---------------------------------------------------------------------------
__device__ bf16 g_Phi[(size_t)B_SZ * T_SZ * 128];    // pattern [b][t][m]
__device__ bf16 g_Plo[(size_t)B_SZ * T_SZ * 128];
__device__ bf16 g_Hhi[(size_t)B_SZ * T_SZ * 1024];   // hidden [b][t][<=1024]
__device__ bf16 g_Hlo[(size_t)B_SZ * T_SZ * 1024];
__device__ bf16 g_Qhi[(size_t)B_SZ * T_SZ * 128];
__device__ bf16 g_Qlo[(size_t)B_SZ * T_SZ * 128];
__device__ bf16 g_Khi[(size_t)B_SZ * T_SZ * 128];
__device__ bf16 g_Klo[(size_t)B_SZ * T_SZ * 128];
__device__ bf16 g_Vhi[(size_t)B_SZ * 128 * T_SZ];    // value [b][m][t]
__device__ bf16 g_Vlo[(size_t)B_SZ * 128 * T_SZ];
__device__ bf16 g_Athi[(size_t)B_SZ * T_SZ * 128];   // attn out [b][q][m]
__device__ bf16 g_Atlo[(size_t)B_SZ * T_SZ * 128];
__device__ bf16 g_W1h[1024 * 128],  g_W1l[1024 * 128];   // [Wq1;Wk1]
__device__ bf16 g_W2qh[128 * 512],  g_W2ql[128 * 512];
__device__ bf16 g_W2kh[128 * 512],  g_W2kl[128 * 512];
__device__ bf16 g_Wo1h[512 * 128],  g_Wo1l[512 * 128];
__device__ bf16 g_Wo2h[128 * 512],  g_Wo2l[128 * 512];
__device__ float g_bcat[1024];                            // [bq1;bk1]

// ---------------------------------------------------------------------------
// Helpers
// ---------------------------------------------------------------------------
__device__ __forceinline__ void mma16816(float* d, const uint32_t* a,
                                         const uint32_t* b) {
    asm volatile(
        "mma.sync.aligned.m16n8k16.row.col.f32.bf16.bf16.f32 "
        "{%0,%1,%2,%3}, {%4,%5,%6,%7}, {%8,%9}, {%0,%1,%2,%3};\n"
        : "+f"(d[0]), "+f"(d[1]), "+f"(d[2]), "+f"(d[3])
        : "r"(a[0]), "r"(a[1]), "r"(a[2]), "r"(a[3]), "r"(b[0]), "r"(b[1]));
}
__device__ __forceinline__ void split2(float v, bf16& h, bf16& l) {
    h = __float2bfloat16(v);
    l = __float2bfloat16(v - __bfloat162float(h));
}
__device__ __forceinline__ uint32_t smem_u32(const void* p) {
    uint32_t a;
    asm("{ .reg .u64 t; cvta.to.shared.u64 t, %1; cvt.u32.u64 %0, t; }"
        : "=r"(a) : "l"(p));
    return a;
}
#define CPA16(s, g) \
    asm volatile("cp.async.cg.shared.global [%0], [%1], 16;\n" \
        :: "r"(s), "l"(g))
#define CPC() asm volatile("cp.async.commit_group;\n" ::: "memory")
#define CPW(n) asm volatile("cp.async.wait_group %0;\n" :: "n"(n) : "memory")

// ---------------------------------------------------------------------------
// Conversions (run once, outside hot loops)
// ---------------------------------------------------------------------------
__global__ void __launch_bounds__(256) conv_T_split(const float* __restrict__ p,
                                                    bf16* __restrict__ hi,
                                                    bf16* __restrict__ lo) {
    __shared__ float s[32][33];
    const int b = blockIdx.z, t0 = blockIdx.x * 32, m0 = blockIdx.y * 32;
    const int tid = threadIdx.x;
#pragma unroll
    for (int u = 0; u < 4; u++) {
        int lin = tid + u * 256;
        int mm = lin >> 5, tt = lin & 31;
        s[mm][tt] = p[((long)b * M_SZ + m0 + mm) * T_SZ + t0 + tt];
    }
    __syncthreads();
#pragma unroll
    for (int u = 0; u < 4; u++) {
        int lin = tid + u * 256;
        int tt = lin >> 5, mm = lin & 31;
        bf16 h, l; split2(s[mm][tt], h, l);
        long o = ((long)b * T_SZ + t0 + tt) * M_SZ + m0 + mm;
        hi[o] = h; lo[o] = l;
    }
}

__global__ void conv_split(const float* __restrict__ x, bf16* __restrict__ hi,
                           bf16* __restrict__ lo, long n) {
    for (long i = (long)blockIdx.x * blockDim.x + threadIdx.x; i < n;
         i += (long)gridDim.x * blockDim.x) {
        bf16 h, l; split2(x[i], h, l);
        hi[i] = h; lo[i] = l;
    }
}

__global__ void bcat_kernel(const float* __restrict__ b0,
                            const float* __restrict__ b1,
                            float* __restrict__ dst) {
    int t = threadIdx.x;
    dst[t] = b0[t];
    dst[512 + t] = b1[t];
}

// ---------------------------------------------------------------------------
// GEMM (bf16x3 HMMA, cp.async double-buffered):
//   D[i][j] = sum_k A[i][k]*W[j][k] + bias[j]
// MODE1=0: split bf16 out (Yhi/Ylo, ldY);  MODE1=1: fp32 out[(b*128+j)*2049+i]
// ---------------------------------------------------------------------------
#define LDA 40                      // halves; 80B row stride (16B-aligned)
#define GPLANE 5120                 // halves per plane (128*40)
#define GSTAGE (4 * GPLANE)         // halves per stage
#define GEMM_SMEM (2 * GSTAGE * 2 + 512)

template<int ACT, int MODE1>
__global__ void __launch_bounds__(256, 1) gemm_cp(
    const bf16* __restrict__ Ahi, const bf16* __restrict__ Alo,
    const bf16* __restrict__ Whi, const bf16* __restrict__ Wlo,
    const float* __restrict__ bias,
    bf16* __restrict__ Yhi, bf16* __restrict__ Ylo, float* __restrict__ Yf,
    int K, int ldA, long strideA, int ldY, long strideY)
{
    extern __shared__ __align__(16) char smem[];
    bf16* S = (bf16*)smem;
    float* sbias = (float*)(smem + 2 * GSTAGE * 2);
    const uint32_t sb = smem_u32(smem);
    const int tid = threadIdx.x, lane = tid & 31, wid = tid >> 5;
    const int gID = lane >> 2, thID = lane & 3;
    const int b = blockIdx.z, i0 = blockIdx.x * 128, j0 = blockIdx.y * 128;
    const int wM = (wid >> 1) * 32, wN = (wid & 1) * 64;

    if (tid < 128) sbias[tid] = bias[j0 + tid];

    const bf16* Abh = Ahi + (long)b * strideA + (long)i0 * ldA;
    const bf16* Abl = Alo + (long)b * strideA + (long)i0 * ldA;
    const bf16* Wbh = Whi + (long)j0 * K;
    const bf16* Wbl = Wlo + (long)j0 * K;

    float acc[2][8][4];
#pragma unroll
    for (int mt = 0; mt < 2; mt++)
#pragma unroll
        for (int nt = 0; nt < 8; nt++)
#pragma unroll
            for (int e = 0; e < 4; e++) acc[mt][nt][e] = 0.f;

    const int nch = K >> 5;

    // fill stage st with k-chunk k0
    auto fill = [&](int st, int k0) {
        const bf16* srcs[4] = {Abh, Abl, Wbh, Wbl};
        const int lds[4] = {ldA, ldA, K, K};
#pragma unroll
        for (int p = 0; p < 4; p++) {
#pragma unroll
            for (int u = 0; u < 2; u++) {
                int c = tid + u * 256;
                int r = c >> 2, off = (c & 3) * 16;
                uint32_t sa = sb + (st * GSTAGE + p * GPLANE + r * LDA) * 2 + off;
                const char* ga = (const char*)(srcs[p] + (long)r * lds[p] + k0) + off;
                CPA16(sa, ga);
            }
        }
    };

    fill(0, 0); CPC();
    for (int ch = 0; ch < nch; ch++) {
        if (ch + 1 < nch) fill((ch + 1) & 1, (ch + 1) * 32);
        CPC();
        CPW(1);
        __syncthreads();
        const int st = ch & 1;
        bf16* Ah = S + st * GSTAGE;
        bf16* Al = Ah + GPLANE;
        bf16* Bh = Al + GPLANE;
        bf16* Bl = Bh + GPLANE;
#pragma unroll
        for (int ks = 0; ks < 2; ks++) {
            const int kb = ks * 16 + thID * 2;
            uint32_t ah[2][4], al[2][4], bh[8][2], bl[8][2];
#pragma unroll
            for (int mt = 0; mt < 2; mt++) {
                int r = wM + mt * 16 + gID;
                ah[mt][0] = *(const uint32_t*)&Ah[r * LDA + kb];
                ah[mt][1] = *(const uint32_t*)&Ah[(r + 8) * LDA + kb];
                ah[mt][2] = *(const uint32_t*)&Ah[r * LDA + kb + 8];
                ah[mt][3] = *(const uint32_t*)&Ah[(r + 8) * LDA + kb + 8];
                al[mt][0] = *(const uint32_t*)&Al[r * LDA + kb];
                al[mt][1] = *(const uint32_t*)&Al[(r + 8) * LDA + kb];
                al[mt][2] = *(const uint32_t*)&Al[r * LDA + kb + 8];
                al[mt][3] = *(const uint32_t*)&Al[(r + 8) * LDA + kb + 8];
            }
#pragma unroll
            for (int nt = 0; nt < 8; nt++) {
                int rn = wN + nt * 8 + gID;
                bh[nt][0] = *(const uint32_t*)&Bh[rn * LDA + kb];
                bh[nt][1] = *(const uint32_t*)&Bh[rn * LDA + kb + 8];
                bl[nt][0] = *(const uint32_t*)&Bl[rn * LDA + kb];
                bl[nt][1] = *(const uint32_t*)&Bl[rn * LDA + kb + 8];
            }
#pragma unroll
            for (int mt = 0; mt < 2; mt++)
#pragma unroll
                for (int nt = 0; nt < 8; nt++) {
                    mma16816(acc[mt][nt], ah[mt], bh[nt]);
                    mma16816(acc[mt][nt], ah[mt], bl[nt]);
                    mma16816(acc[mt][nt], al[mt], bh[nt]);
                }
        }
        __syncthreads();
    }

    // epilogue
#pragma unroll
    for (int mt = 0; mt < 2; mt++)
#pragma unroll
        for (int nt = 0; nt < 8; nt++) {
            int i_ = wM + mt * 16 + gID;
            int j_ = wN + nt * 8 + thID * 2;
            float v0 = acc[mt][nt][0] + sbias[j_];
            float v1 = acc[mt][nt][1] + sbias[j_ + 1];
            float v2 = acc[mt][nt][2] + sbias[j_];
            float v3 = acc[mt][nt][3] + sbias[j_ + 1];
            if (ACT) {
                v0 = v0 > 0.f ? v0 : 0.01f * v0;
                v1 = v1 > 0.f ? v1 : 0.01f * v1;
                v2 = v2 > 0.f ? v2 : 0.01f * v2;
                v3 = v3 > 0.f ? v3 : 0.01f * v3;
            }
            if (!MODE1) {
                long base = (long)b * strideY + (long)(i0 + i_) * ldY + j0 + j_;
                bf162 h2, l2;
                split2(v0, h2.x, l2.x); split2(v1, h2.y, l2.y);
                *(bf162*)&Yhi[base] = h2;
                *(bf162*)&Ylo[base] = l2;
                split2(v2, h2.x, l2.x); split2(v3, h2.y, l2.y);
                *(bf162*)&Yhi[base + 8L * ldY] = h2;
                *(bf162*)&Ylo[base + 8L * ldY] = l2;
            } else {
                long c0 = ((long)b * 128 + j0 + j_) * 2049 + i0 + i_;
                Yf[c0] = v0;
                Yf[c0 + 2049] = v1;
                Yf[c0 + 8] = v2;
                Yf[c0 + 2049 + 8] = v3;
            }
        }
}

// ---------------------------------------------------------------------------
// Fused attention (bf16x3 HMMA, cp.async). CTA = (q-tile 128, batch).
// ---------------------------------------------------------------------------
#define LDW 136
#define APLANE (128 * LDW)                    // halves per plane
#define ATT_SMEM (6 * APLANE * 2 + 256 * 4 + 128 * 4)

__global__ void __launch_bounds__(256, 1) attn_cp(
    const bf16* __restrict__ Qhi, const bf16* __restrict__ Qlo,
    const bf16* __restrict__ Khi, const bf16* __restrict__ Klo,
    const bf16* __restrict__ Vhi, const bf16* __restrict__ Vlo,
    bf16* __restrict__ Ahi, bf16* __restrict__ Alo)
{
    extern __shared__ __align__(16) char smem[];
    bf16* Qh  = (bf16*)smem;
    bf16* Ql  = Qh + APLANE;
    bf16* KVh = Ql + APLANE;
    bf16* KVl = KVh + APLANE;
    bf16* Wh  = KVl + APLANE;
    bf16* Wl  = Wh + APLANE;
    float* rsP    = (float*)(Wl + APLANE);   // [2][128]
    float* srecip = rsP + 256;
    const uint32_t sb = smem_u32(smem);

    const int tid = threadIdx.x, lane = tid & 31, wid = tid >> 5;
    const int gID = lane >> 2, thID = lane & 3;
    const int b = blockIdx.y, q0 = blockIdx.x * 128;
    const int wM = (wid >> 1) * 32, wN = (wid & 1) * 64;
    const float cdiag = 0.97790291308792045f;  // 1 - 1/sqrt(2048)

    // cp.async one 128x128 plane (16B chunks, 8 per thread)
    auto fillp = [&](int plane, const bf16* src, long base, int ld) {
#pragma unroll
        for (int u = 0; u < 8; u++) {
            int c = tid + u * 256;
            int r = c >> 4, off = (c & 15) * 16;
            uint32_t sa = sb + (plane * APLANE + r * LDW) * 2 + off;
            const char* ga = (const char*)(src + base + (long)r * ld) + off;
            CPA16(sa, ga);
        }
    };

    const long qbase = ((long)b * T_SZ + q0) * 128;
    fillp(0, Qhi, qbase, 128);
    fillp(1, Qlo, qbase, 128);
    CPC();
    fillp(2, Khi, ((long)b * T_SZ) * 128, 128);
    fillp(3, Klo, ((long)b * T_SZ) * 128, 128);
    CPC();
    if (tid < 256) rsP[tid] = 0.f;

    float accv[2][8][4];
#pragma unroll
    for (int mt = 0; mt < 2; mt++)
#pragma unroll
        for (int nt = 0; nt < 8; nt++)
#pragma unroll
            for (int e = 0; e < 4; e++) accv[mt][nt][e] = 0.f;

    CPW(0);
    __syncthreads();

    for (int kt = 0; kt < 16; kt++) {
        // ---- S = Q K^T ----
        float accs[2][8][4];
#pragma unroll
        for (int mt = 0; mt < 2; mt++)
#pragma unroll
            for (int nt = 0; nt < 8; nt++)
#pragma unroll
                for (int e = 0; e < 4; e++) accs[mt][nt][e] = 0.f;
#pragma unroll
        for (int ks = 0; ks < 8; ks++) {
            const int kb = ks * 16 + thID * 2;
            uint32_t ah[2][4], al[2][4], bh[8][2], bl[8][2];
#pragma unroll
            for (int mt = 0; mt < 2; mt++) {
                int r = wM + mt * 16 + gID;
                ah[mt][0] = *(const uint32_t*)&Qh[r * LDW + kb];
                ah[mt][1] = *(const uint32_t*)&Qh[(r + 8) * LDW + kb];
                ah[mt][2] = *(const uint32_t*)&Qh[r * LDW + kb + 8];
                ah[mt][3] = *(const uint32_t*)&Qh[(r + 8) * LDW + kb + 8];
                al[mt][0] = *(const uint32_t*)&Ql[r * LDW + kb];
                al[mt][1] = *(const uint32_t*)&Ql[(r + 8) * LDW + kb];
                al[mt][2] = *(const uint32_t*)&Ql[r * LDW + kb + 8];
                al[mt][3] = *(const uint32_t*)&Ql[(r + 8) * LDW + kb + 8];
            }
#pragma unroll
            for (int nt = 0; nt < 8; nt++) {
                int rn = wN + nt * 8 + gID;
                bh[nt][0] = *(const uint32_t*)&KVh[rn * LDW + kb];
                bh[nt][1] = *(const uint32_t*)&KVh[rn * LDW + kb + 8];
                bl[nt][0] = *(const uint32_t*)&KVl[rn * LDW + kb];
                bl[nt][1] = *(const uint32_t*)&KVl[rn * LDW + kb + 8];
            }
#pragma unroll
            for (int mt = 0; mt < 2; mt++)
#pragma unroll
                for (int nt = 0; nt < 8; nt++) {
                    mma16816(accs[mt][nt], ah[mt], bh[nt]);
                    mma16816(accs[mt][nt], ah[mt], bl[nt]);
                    mma16816(accs[mt][nt], al[mt], bh[nt]);
                }
        }
        __syncthreads();   // all warps done reading K planes

        // overlap: V tile load while we do exp/split
        fillp(2, Vhi, (long)b * 128 * T_SZ + kt * 128, T_SZ);
        fillp(3, Vlo, (long)b * 128 * T_SZ + kt * 128, T_SZ);
        CPC();

        // ---- w = exp(exp(S diag-adj)), rowsum, split -> W planes ----
        float rp[2][2] = {{0.f, 0.f}, {0.f, 0.f}};
#pragma unroll
        for (int mt = 0; mt < 2; mt++)
#pragma unroll
            for (int nt = 0; nt < 8; nt++) {
                int ql = wM + mt * 16 + gID;
                int kl = wN + nt * 8 + thID * 2;
                int qi = q0 + ql, kk = kt * 128 + kl;
                float x0 = accs[mt][nt][0], x1 = accs[mt][nt][1];
                float x2 = accs[mt][nt][2], x3 = accs[mt][nt][3];
                if (qi == kk)         x0 *= cdiag;
                if (qi == kk + 1)     x1 *= cdiag;
                if (qi + 8 == kk)     x2 *= cdiag;
                if (qi + 8 == kk + 1) x3 *= cdiag;
                float w0 = __expf(__expf(x0));
                float w1 = __expf(__expf(x1));
                float w2 = __expf(__expf(x2));
                float w3 = __expf(__expf(x3));
                rp[mt][0] += w0 + w1;
                rp[mt][1] += w2 + w3;
                bf162 h2, l2;
                split2(w0, h2.x, l2.x); split2(w1, h2.y, l2.y);
                *(bf162*)&Wh[ql * LDW + kl] = h2;
                *(bf162*)&Wl[ql * LDW + kl] = l2;
                split2(w2, h2.x, l2.x); split2(w3, h2.y, l2.y);
                *(bf162*)&Wh[(ql + 8) * LDW + kl] = h2;
                *(bf162*)&Wl[(ql + 8) * LDW + kl] = l2;
            }
#pragma unroll
        for (int mt = 0; mt < 2; mt++)
#pragma unroll
            for (int h = 0; h < 2; h++) {
                float s = rp[mt][h];
                s += __shfl_xor_sync(0xffffffffu, s, 1);
                s += __shfl_xor_sync(0xffffffffu, s, 2);
                if (thID == 0)
                    rsP[(wid & 1) * 128 + wM + mt * 16 + gID + h * 8] += s;
            }
        CPW(0);
        __syncthreads();   // V ready, W visible

        // ---- AV += W V^T ----
#pragma unroll
        for (int ks = 0; ks < 8; ks++) {
            const int kb = ks * 16 + thID * 2;
            uint32_t ah[2][4], al[2][4], bh[8][2], bl[8][2];
#pragma unroll
            for (int mt = 0; mt < 2; mt++) {
                int r = wM + mt * 16 + gID;
                ah[mt][0] = *(const uint32_t*)&Wh[r * LDW + kb];
                ah[mt][1] = *(const uint32_t*)&Wh[(r + 8) * LDW + kb];
                ah[mt][2] = *(const uint32_t*)&Wh[r * LDW + kb + 8];
                ah[mt][3] = *(const uint32_t*)&Wh[(r + 8) * LDW + kb + 8];
                al[mt][0] = *(const uint32_t*)&Wl[r * LDW + kb];
                al[mt][1] = *(const uint32_t*)&Wl[(r + 8) * LDW + kb];
                al[mt][2] = *(const uint32_t*)&Wl[r * LDW + kb + 8];
                al[mt][3] = *(const uint32_t*)&Wl[(r + 8) * LDW + kb + 8];
            }
#pragma unroll
            for (int nt = 0; nt < 8; nt++) {
                int rn = wN + nt * 8 + gID;
                bh[nt][0] = *(const uint32_t*)&KVh[rn * LDW + kb];
                bh[nt][1] = *(const uint32_t*)&KVh[rn * LDW + kb + 8];
                bl[nt][0] = *(const uint32_t*)&KVl[rn * LDW + kb];
                bl[nt][1] = *(const uint32_t*)&KVl[rn * LDW + kb + 8];
            }
#pragma unroll
            for (int mt = 0; mt < 2; mt++)
#pragma unroll
                for (int nt = 0; nt < 8; nt++) {
                    mma16816(accv[mt][nt], ah[mt], bh[nt]);
                    mma16816(accv[mt][nt], ah[mt], bl[nt]);
                    mma16816(accv[mt][nt], al[mt], bh[nt]);
                }
        }
        __syncthreads();   // done reading V planes

        if (kt + 1 < 16) {
            fillp(2, Khi, ((long)b * T_SZ + (kt + 1) * 128) * 128, 128);
            fillp(3, Klo, ((long)b * T_SZ + (kt + 1) * 128) * 128, 128);
            CPC();
            CPW(0);
            __syncthreads();
        }
    }
    __syncthreads();
    if (tid < 128) srecip[tid] = 1.0f / (rsP[tid] + rsP[128 + tid]);
    __syncthreads();

    // out[b][q][m] = AV[q][m] / rowsum[q]  (split bf16)
#pragma unroll
    for (int mt = 0; mt < 2; mt++)
#pragma unroll
        for (int nt = 0; nt < 8; nt++) {
            int i_ = wM + mt * 16 + gID;
            int j_ = wN + nt * 8 + thID * 2;
            float r0 = srecip[i_], r1 = srecip[i_ + 8];
            long base = ((long)b * T_SZ + q0 + i_) * 128 + j_;
            bf162 h2, l2;
            split2(accv[mt][nt][0] * r0, h2.x, l2.x);
            split2(accv[mt][nt][1] * r0, h2.y, l2.y);
            *(bf162*)&Ahi[base] = h2;
            *(bf162*)&Alo[base] = l2;
            split2(accv[mt][nt][2] * r1, h2.x, l2.x);
            split2(accv[mt][nt][3] * r1, h2.y, l2.y);
            *(bf162*)&Ahi[base + 8L * 128] = h2;
            *(bf162*)&Alo[base + 8L * 128] = l2;
        }
}

// ---------------------------------------------------------------------------
// Windowed branch (Tq=1 => uniform softmax => mean of value[...,33:2047]) + Wo
// ---------------------------------------------------------------------------
__global__ void __launch_bounds__(256) tail_kernel(
    const float* __restrict__ value,
    const float* __restrict__ Wo1, const float* __restrict__ bo1,
    const float* __restrict__ Wo2, const float* __restrict__ bo2,
    float* __restrict__ out)
{
    __shared__ float ex[128];
    __shared__ float hv[512];
    const int b = blockIdx.x, tid = threadIdx.x;
    const int w = tid >> 5, lane = tid & 31;

    for (int it = 0; it < 16; it++) {
        int m = it * 8 + w;
        const float* vp = value + ((long)b * M_SZ + m) * T_SZ;
        float s = 0.f;
        for (int k = 33 + lane; k < 2047; k += 32) s += vp[k];
#pragma unroll
        for (int o = 16; o; o >>= 1) s += __shfl_xor_sync(0xffffffffu, s, o);
        if (lane == 0) ex[m] = s * (1.0f / 2014.0f);
    }
    __syncthreads();
    for (int h = tid; h < 512; h += 256) {
        float s = bo1[h];
#pragma unroll 4
        for (int m = 0; m < 128; m++) s += Wo1[h * 128 + m] * ex[m];
        hv[h] = s;
    }
    __syncthreads();
    if (tid < 128) {
        float s = bo2[tid];
#pragma unroll 4
        for (int h = 0; h < 512; h++) s += Wo2[tid * 512 + h] * hv[h];
        s = s > 0.f ? s : 0.01f * s;
        out[((long)b * M_SZ + tid) * 2049 + 2048] = s;
    }
}

// ---------------------------------------------------------------------------
extern "C" void kernel_launch(void* const* d_in, const int* in_sizes, int n_in,
                              void* d_out, int out_size) {
    const int ofs = (n_in >= 15) ? 3 : 2;
    const float* pattern = (const float*)d_in[0];
    const float* value   = (const float*)d_in[1];
    const float* Wq1 = (const float*)d_in[ofs + 0];
    const float* bq1 = (const float*)d_in[ofs + 1];
    const float* Wq2 = (const float*)d_in[ofs + 2];
    const float* bq2 = (const float*)d_in[ofs + 3];
    const float* Wk1 = (const float*)d_in[ofs + 4];
    const float* bk1 = (const float*)d_in[ofs + 5];
    const float* Wk2 = (const float*)d_in[ofs + 6];
    const float* bk2 = (const float*)d_in[ofs + 7];
    const float* Wo1 = (const float*)d_in[ofs + 8];
    const float* bo1 = (const float*)d_in[ofs + 9];
    const float* Wo2 = (const float*)d_in[ofs + 10];
    const float* bo2 = (const float*)d_in[ofs + 11];
    float* out = (float*)d_out;

    bf16 *Phi, *Plo, *Hhi, *Hlo, *Qhi, *Qlo, *Khi, *Klo, *Vhi, *Vlo;
    bf16 *Athi, *Atlo, *W1h, *W1l, *W2qh, *W2ql, *W2kh, *W2kl;
    bf16 *Wo1h, *Wo1l, *Wo2h, *Wo2l;
    float* bcat;
    cudaGetSymbolAddress((void**)&Phi,  g_Phi);
    cudaGetSymbolAddress((void**)&Plo,  g_Plo);
    cudaGetSymbolAddress((void**)&Hhi,  g_Hhi);
    cudaGetSymbolAddress((void**)&Hlo,  g_Hlo);
    cudaGetSymbolAddress((void**)&Qhi,  g_Qhi);
    cudaGetSymbolAddress((void**)&Qlo,  g_Qlo);
    cudaGetSymbolAddress((void**)&Khi,  g_Khi);
    cudaGetSymbolAddress((void**)&Klo,  g_Klo);
    cudaGetSymbolAddress((void**)&Vhi,  g_Vhi);
    cudaGetSymbolAddress((void**)&Vlo,  g_Vlo);
    cudaGetSymbolAddress((void**)&Athi, g_Athi);
    cudaGetSymbolAddress((void**)&Atlo, g_Atlo);
    cudaGetSymbolAddress((void**)&W1h,  g_W1h);
    cudaGetSymbolAddress((void**)&W1l,  g_W1l);
    cudaGetSymbolAddress((void**)&W2qh, g_W2qh);
    cudaGetSymbolAddress((void**)&W2ql, g_W2ql);
    cudaGetSymbolAddress((void**)&W2kh, g_W2kh);
    cudaGetSymbolAddress((void**)&W2kl, g_W2kl);
    cudaGetSymbolAddress((void**)&Wo1h, g_Wo1h);
    cudaGetSymbolAddress((void**)&Wo1l, g_Wo1l);
    cudaGetSymbolAddress((void**)&Wo2h, g_Wo2h);
    cudaGetSymbolAddress((void**)&Wo2l, g_Wo2l);
    cudaGetSymbolAddress((void**)&bcat, g_bcat);

    cudaFuncSetAttribute(gemm_cp<0,0>, cudaFuncAttributeMaxDynamicSharedMemorySize, GEMM_SMEM);
    cudaFuncSetAttribute(gemm_cp<1,0>, cudaFuncAttributeMaxDynamicSharedMemorySize, GEMM_SMEM);
    cudaFuncSetAttribute(gemm_cp<1,1>, cudaFuncAttributeMaxDynamicSharedMemorySize, GEMM_SMEM);
    cudaFuncSetAttribute(attn_cp,      cudaFuncAttributeMaxDynamicSharedMemorySize, ATT_SMEM);

    // one-time conversions
    conv_T_split<<<dim3(64, 4, 16), 256>>>(pattern, Phi, Plo);
    conv_split<<<512, 256>>>(value, Vhi, Vlo, (long)B_SZ * 128 * T_SZ);
    conv_split<<<64, 256>>>(Wq1, W1h, W1l, 512 * 128);
    conv_split<<<64, 256>>>(Wk1, W1h + 512 * 128, W1l + 512 * 128, 512 * 128);
    conv_split<<<64, 256>>>(Wq2, W2qh, W2ql, 128 * 512);
    conv_split<<<64, 256>>>(Wk2, W2kh, W2kl, 128 * 512);
    conv_split<<<64, 256>>>(Wo1, Wo1h, Wo1l, 512 * 128);
    conv_split<<<64, 256>>>(Wo2, Wo2h, Wo2l, 128 * 512);
    bcat_kernel<<<1, 512>>>(bq1, bk1, bcat);

    const long sPM = (long)T_SZ * 128;

    // fused q+k layer-1: H[b][t][0:1024] (q half then k half)
    gemm_cp<0,0><<<dim3(16, 8, 16), 256, GEMM_SMEM>>>(
        Phi, Plo, W1h, W1l, bcat, Hhi, Hlo, nullptr,
        128, 128, sPM, 1024, (long)T_SZ * 1024);
    // layer-2 q / k
    gemm_cp<1,0><<<dim3(16, 1, 16), 256, GEMM_SMEM>>>(
        Hhi, Hlo, W2qh, W2ql, bq2, Qhi, Qlo, nullptr,
        512, 1024, (long)T_SZ * 1024, 128, sPM);
    gemm_cp<1,0><<<dim3(16, 1, 16), 256, GEMM_SMEM>>>(
        Hhi + 512, Hlo + 512, W2kh, W2kl, bk2, Khi, Klo, nullptr,
        512, 1024, (long)T_SZ * 1024, 128, sPM);
    // attention
    attn_cp<<<dim3(16, 16), 256, ATT_SMEM>>>(Qhi, Qlo, Khi, Klo, Vhi, Vlo,
                                             Athi, Atlo);
    // output MLP
    gemm_cp<0,0><<<dim3(16, 4, 16), 256, GEMM_SMEM>>>(
        Athi, Atlo, Wo1h, Wo1l, bo1, Hhi, Hlo, nullptr,
        128, 128, sPM, 512, (long)T_SZ * 512);
    gemm_cp<1,1><<<dim3(16, 1, 16), 256, GEMM_SMEM>>>(
        Hhi, Hlo, Wo2h, Wo2l, bo2, nullptr, nullptr, out,
        512, 512, (long)T_SZ * 512, 0, 0);
    // windowed branch -> out[..., 2048]
    tail_kernel<<<B_SZ, 256>>>(value, Wo1, bo1, Wo2, bo2, out);
}

// round 12
// speedup vs baseline: 2.4878x; 1.0004x over previous
#include <cuda_runtime.h>
#include <cuda_bf16.h>
#include <cstdint>

typedef __nv_bfloat16  bf16;
typedef __nv_bfloat162 bf162;

#define B_SZ 16
#define M_SZ 128
#define T_SZ 2048
#define H_SZ 512

// ---------------------------------------------------------------------------
// Scratch (device globals, allocation-free). Separate bf16 hi/lo planes.
// ---------------------------------------------------------------------------
__device__ bf16 g_Phi[(size_t)B_SZ * T_SZ * 128];    // pattern [b][t][m]
__device__ bf16 g_Plo[(size_t)B_SZ * T_SZ * 128];
__device__ bf16 g_Hhi[(size_t)B_SZ * T_SZ * 1024];   // hidden [b][t][<=1024]
__device__ bf16 g_Hlo[(size_t)B_SZ * T_SZ * 1024];
__device__ bf16 g_Qhi[(size_t)B_SZ * T_SZ * 128];
__device__ bf16 g_Qlo[(size_t)B_SZ * T_SZ * 128];
__device__ bf16 g_Khi[(size_t)B_SZ * T_SZ * 128];
__device__ bf16 g_Klo[(size_t)B_SZ * T_SZ * 128];
__device__ bf16 g_Vhi[(size_t)B_SZ * 128 * T_SZ];    // value [b][m][t]
__device__ bf16 g_Vlo[(size_t)B_SZ * 128 * T_SZ];
__device__ bf16 g_Athi[(size_t)B_SZ * T_SZ * 128];   // attn out [b][q][m]
__device__ bf16 g_Atlo[(size_t)B_SZ * T_SZ * 128];
__device__ bf16 g_W1h[1024 * 128],  g_W1l[1024 * 128];   // [Wq1;Wk1]
__device__ bf16 g_W2qh[128 * 512],  g_W2ql[128 * 512];
__device__ bf16 g_W2kh[128 * 512],  g_W2kl[128 * 512];
__device__ bf16 g_Wo1h[512 * 128],  g_Wo1l[512 * 128];
__device__ bf16 g_Wo2h[128 * 512],  g_Wo2l[128 * 512];
__device__ float g_bcat[1024];                            // [bq1;bk1]

// ---------------------------------------------------------------------------
// Helpers
// ---------------------------------------------------------------------------
__device__ __forceinline__ void mma16816(float* d, const uint32_t* a,
                                         const uint32_t* b) {
    asm volatile(
        "mma.sync.aligned.m16n8k16.row.col.f32.bf16.bf16.f32 "
        "{%0,%1,%2,%3}, {%4,%5,%6,%7}, {%8,%9}, {%0,%1,%2,%3};\n"
        : "+f"(d[0]), "+f"(d[1]), "+f"(d[2]), "+f"(d[3])
        : "r"(a[0]), "r"(a[1]), "r"(a[2]), "r"(a[3]), "r"(b[0]), "r"(b[1]));
}
__device__ __forceinline__ void split2(float v, bf16& h, bf16& l) {
    h = __float2bfloat16(v);
    l = __float2bfloat16(v - __bfloat162float(h));
}
__device__ __forceinline__ uint32_t smem_u32(const void* p) {
    uint32_t a;
    asm("{ .reg .u64 t; cvta.to.shared.u64 t, %1; cvt.u32.u64 %0, t; }"
        : "=r"(a) : "l"(p));
    return a;
}
#define CPA16(s, g) \
    asm volatile("cp.async.cg.shared.global [%0], [%1], 16;\n" \
        :: "r"(s), "l"(g))
#define CPC() asm volatile("cp.async.commit_group;\n" ::: "memory")
#define CPW(n) asm volatile("cp.async.wait_group %0;\n" :: "n"(n) : "memory")

// ---------------------------------------------------------------------------
// Conversions (run once, outside hot loops)
// ---------------------------------------------------------------------------
__global__ void __launch_bounds__(256) conv_T_split(const float* __restrict__ p,
                                                    bf16* __restrict__ hi,
                                                    bf16* __restrict__ lo) {
    __shared__ float s[32][33];
    const int b = blockIdx.z, t0 = blockIdx.x * 32, m0 = blockIdx.y * 32;
    const int tid = threadIdx.x;
#pragma unroll
    for (int u = 0; u < 4; u++) {
        int lin = tid + u * 256;
        int mm = lin >> 5, tt = lin & 31;
        s[mm][tt] = p[((long)b * M_SZ + m0 + mm) * T_SZ + t0 + tt];
    }
    __syncthreads();
#pragma unroll
    for (int u = 0; u < 4; u++) {
        int lin = tid + u * 256;
        int tt = lin >> 5, mm = lin & 31;
        bf16 h, l; split2(s[mm][tt], h, l);
        long o = ((long)b * T_SZ + t0 + tt) * M_SZ + m0 + mm;
        hi[o] = h; lo[o] = l;
    }
}

__global__ void conv_split(const float* __restrict__ x, bf16* __restrict__ hi,
                           bf16* __restrict__ lo, long n) {
    for (long i = (long)blockIdx.x * blockDim.x + threadIdx.x; i < n;
         i += (long)gridDim.x * blockDim.x) {
        bf16 h, l; split2(x[i], h, l);
        hi[i] = h; lo[i] = l;
    }
}

__global__ void bcat_kernel(const float* __restrict__ b0,
                            const float* __restrict__ b1,
                            float* __restrict__ dst) {
    int t = threadIdx.x;
    dst[t] = b0[t];
    dst[512 + t] = b1[t];
}

// ---------------------------------------------------------------------------
// GEMM (bf16x3 HMMA, cp.async double-buffered, product-major MMA order):
//   D[i][j] = sum_k A[i][k]*W[j][k] + bias[j]
// MODE1=0: split bf16 out (Yhi/Ylo, ldY);  MODE1=1: fp32 out[(b*128+j)*2049+i]
// ---------------------------------------------------------------------------
#define LDA 40                      // halves; 80B row stride (16B-aligned)
#define GPLANE 5120                 // halves per plane (128*40)
#define GSTAGE (4 * GPLANE)         // halves per stage
#define GEMM_SMEM (2 * GSTAGE * 2 + 512)

template<int ACT, int MODE1>
__global__ void __launch_bounds__(256, 1) gemm_cp(
    const bf16* __restrict__ Ahi, const bf16* __restrict__ Alo,
    const bf16* __restrict__ Whi, const bf16* __restrict__ Wlo,
    const float* __restrict__ bias,
    bf16* __restrict__ Yhi, bf16* __restrict__ Ylo, float* __restrict__ Yf,
    int K, int ldA, long strideA, int ldY, long strideY)
{
    extern __shared__ __align__(16) char smem[];
    bf16* S = (bf16*)smem;
    float* sbias = (float*)(smem + 2 * GSTAGE * 2);
    const uint32_t sb = smem_u32(smem);
    const int tid = threadIdx.x, lane = tid & 31, wid = tid >> 5;
    const int gID = lane >> 2, thID = lane & 3;
    const int b = blockIdx.z, i0 = blockIdx.x * 128, j0 = blockIdx.y * 128;
    const int wM = (wid >> 1) * 32, wN = (wid & 1) * 64;

    if (tid < 128) sbias[tid] = bias[j0 + tid];

    const bf16* Abh = Ahi + (long)b * strideA + (long)i0 * ldA;
    const bf16* Abl = Alo + (long)b * strideA + (long)i0 * ldA;
    const bf16* Wbh = Whi + (long)j0 * K;
    const bf16* Wbl = Wlo + (long)j0 * K;

    float acc[2][8][4];
#pragma unroll
    for (int mt = 0; mt < 2; mt++)
#pragma unroll
        for (int nt = 0; nt < 8; nt++)
#pragma unroll
            for (int e = 0; e < 4; e++) acc[mt][nt][e] = 0.f;

    const int nch = K >> 5;

    auto fill = [&](int st, int k0) {
        const bf16* srcs[4] = {Abh, Abl, Wbh, Wbl};
        const int lds[4] = {ldA, ldA, K, K};
#pragma unroll
        for (int p = 0; p < 4; p++) {
#pragma unroll
            for (int u = 0; u < 2; u++) {
                int c = tid + u * 256;
                int r = c >> 2, off = (c & 3) * 16;
                uint32_t sa = sb + (st * GSTAGE + p * GPLANE + r * LDA) * 2 + off;
                const char* ga = (const char*)(srcs[p] + (long)r * lds[p] + k0) + off;
                CPA16(sa, ga);
            }
        }
    };

    fill(0, 0); CPC();
    for (int ch = 0; ch < nch; ch++) {
        if (ch + 1 < nch) fill((ch + 1) & 1, (ch + 1) * 32);
        CPC();
        CPW(1);
        __syncthreads();
        const int st = ch & 1;
        bf16* Ah = S + st * GSTAGE;
        bf16* Al = Ah + GPLANE;
        bf16* Bh = Al + GPLANE;
        bf16* Bl = Bh + GPLANE;
#pragma unroll
        for (int ks = 0; ks < 2; ks++) {
            const int kb = ks * 16 + thID * 2;
            uint32_t ah[2][4], al[2][4], bh[8][2], bl[8][2];
#pragma unroll
            for (int mt = 0; mt < 2; mt++) {
                int r = wM + mt * 16 + gID;
                ah[mt][0] = *(const uint32_t*)&Ah[r * LDA + kb];
                ah[mt][1] = *(const uint32_t*)&Ah[(r + 8) * LDA + kb];
                ah[mt][2] = *(const uint32_t*)&Ah[r * LDA + kb + 8];
                ah[mt][3] = *(const uint32_t*)&Ah[(r + 8) * LDA + kb + 8];
                al[mt][0] = *(const uint32_t*)&Al[r * LDA + kb];
                al[mt][1] = *(const uint32_t*)&Al[(r + 8) * LDA + kb];
                al[mt][2] = *(const uint32_t*)&Al[r * LDA + kb + 8];
                al[mt][3] = *(const uint32_t*)&Al[(r + 8) * LDA + kb + 8];
            }
#pragma unroll
            for (int nt = 0; nt < 8; nt++) {
                int rn = wN + nt * 8 + gID;
                bh[nt][0] = *(const uint32_t*)&Bh[rn * LDA + kb];
                bh[nt][1] = *(const uint32_t*)&Bh[rn * LDA + kb + 8];
                bl[nt][0] = *(const uint32_t*)&Bl[rn * LDA + kb];
                bl[nt][1] = *(const uint32_t*)&Bl[rn * LDA + kb + 8];
            }
            // product-major: 16 independent accumulators between same-acc MMAs
#pragma unroll
            for (int p = 0; p < 3; p++) {
#pragma unroll
                for (int mt = 0; mt < 2; mt++)
#pragma unroll
                    for (int nt = 0; nt < 8; nt++)
                        mma16816(acc[mt][nt],
                                 (p == 2) ? al[mt] : ah[mt],
                                 (p == 1) ? bl[nt] : bh[nt]);
            }
        }
        __syncthreads();
    }

    // epilogue
#pragma unroll
    for (int mt = 0; mt < 2; mt++)
#pragma unroll
        for (int nt = 0; nt < 8; nt++) {
            int i_ = wM + mt * 16 + gID;
            int j_ = wN + nt * 8 + thID * 2;
            float v0 = acc[mt][nt][0] + sbias[j_];
            float v1 = acc[mt][nt][1] + sbias[j_ + 1];
            float v2 = acc[mt][nt][2] + sbias[j_];
            float v3 = acc[mt][nt][3] + sbias[j_ + 1];
            if (ACT) {
                v0 = v0 > 0.f ? v0 : 0.01f * v0;
                v1 = v1 > 0.f ? v1 : 0.01f * v1;
                v2 = v2 > 0.f ? v2 : 0.01f * v2;
                v3 = v3 > 0.f ? v3 : 0.01f * v3;
            }
            if (!MODE1) {
                long base = (long)b * strideY + (long)(i0 + i_) * ldY + j0 + j_;
                bf162 h2, l2;
                split2(v0, h2.x, l2.x); split2(v1, h2.y, l2.y);
                *(bf162*)&Yhi[base] = h2;
                *(bf162*)&Ylo[base] = l2;
                split2(v2, h2.x, l2.x); split2(v3, h2.y, l2.y);
                *(bf162*)&Yhi[base + 8L * ldY] = h2;
                *(bf162*)&Ylo[base + 8L * ldY] = l2;
            } else {
                long c0 = ((long)b * 128 + j0 + j_) * 2049 + i0 + i_;
                Yf[c0] = v0;
                Yf[c0 + 2049] = v1;
                Yf[c0 + 8] = v2;
                Yf[c0 + 2049 + 8] = v3;
            }
        }
}

// ---------------------------------------------------------------------------
// Fused attention (bf16x3 HMMA, cp.async, product-major MMA order).
// ---------------------------------------------------------------------------
#define LDW 136
#define APLANE (128 * LDW)                    // halves per plane
#define ATT_SMEM (6 * APLANE * 2 + 256 * 4 + 128 * 4)

__global__ void __launch_bounds__(256, 1) attn_cp(
    const bf16* __restrict__ Qhi, const bf16* __restrict__ Qlo,
    const bf16* __restrict__ Khi, const bf16* __restrict__ Klo,
    const bf16* __restrict__ Vhi, const bf16* __restrict__ Vlo,
    bf16* __restrict__ Ahi, bf16* __restrict__ Alo)
{
    extern __shared__ __align__(16) char smem[];
    bf16* Qh  = (bf16*)smem;
    bf16* Ql  = Qh + APLANE;
    bf16* KVh = Ql + APLANE;
    bf16* KVl = KVh + APLANE;
    bf16* Wh  = KVl + APLANE;
    bf16* Wl  = Wh + APLANE;
    float* rsP    = (float*)(Wl + APLANE);   // [2][128]
    float* srecip = rsP + 256;
    const uint32_t sb = smem_u32(smem);

    const int tid = threadIdx.x, lane = tid & 31, wid = tid >> 5;
    const int gID = lane >> 2, thID = lane & 3;
    const int b = blockIdx.y, q0 = blockIdx.x * 128;
    const int wM = (wid >> 1) * 32, wN = (wid & 1) * 64;
    const float cdiag = 0.97790291308792045f;  // 1 - 1/sqrt(2048)

    auto fillp = [&](int plane, const bf16* src, long base, int ld) {
#pragma unroll
        for (int u = 0; u < 8; u++) {
            int c = tid + u * 256;
            int r = c >> 4, off = (c & 15) * 16;
            uint32_t sa = sb + (plane * APLANE + r * LDW) * 2 + off;
            const char* ga = (const char*)(src + base + (long)r * ld) + off;
            CPA16(sa, ga);
        }
    };

    const long qbase = ((long)b * T_SZ + q0) * 128;
    fillp(0, Qhi, qbase, 128);
    fillp(1, Qlo, qbase, 128);
    CPC();
    fillp(2, Khi, ((long)b * T_SZ) * 128, 128);
    fillp(3, Klo, ((long)b * T_SZ) * 128, 128);
    CPC();
    if (tid < 256) rsP[tid] = 0.f;

    float accv[2][8][4];
#pragma unroll
    for (int mt = 0; mt < 2; mt++)
#pragma unroll
        for (int nt = 0; nt < 8; nt++)
#pragma unroll
            for (int e = 0; e < 4; e++) accv[mt][nt][e] = 0.f;

    CPW(0);
    __syncthreads();

    for (int kt = 0; kt < 16; kt++) {
        // ---- S = Q K^T ----
        float accs[2][8][4];
#pragma unroll
        for (int mt = 0; mt < 2; mt++)
#pragma unroll
            for (int nt = 0; nt < 8; nt++)
#pragma unroll
                for (int e = 0; e < 4; e++) accs[mt][nt][e] = 0.f;
#pragma unroll
        for (int ks = 0; ks < 8; ks++) {
            const int kb = ks * 16 + thID * 2;
            uint32_t ah[2][4], al[2][4], bh[8][2], bl[8][2];
#pragma unroll
            for (int mt = 0; mt < 2; mt++) {
                int r = wM + mt * 16 + gID;
                ah[mt][0] = *(const uint32_t*)&Qh[r * LDW + kb];
                ah[mt][1] = *(const uint32_t*)&Qh[(r + 8) * LDW + kb];
                ah[mt][2] = *(const uint32_t*)&Qh[r * LDW + kb + 8];
                ah[mt][3] = *(const uint32_t*)&Qh[(r + 8) * LDW + kb + 8];
                al[mt][0] = *(const uint32_t*)&Ql[r * LDW + kb];
                al[mt][1] = *(const uint32_t*)&Ql[(r + 8) * LDW + kb];
                al[mt][2] = *(const uint32_t*)&Ql[r * LDW + kb + 8];
                al[mt][3] = *(const uint32_t*)&Ql[(r + 8) * LDW + kb + 8];
            }
#pragma unroll
            for (int nt = 0; nt < 8; nt++) {
                int rn = wN + nt * 8 + gID;
                bh[nt][0] = *(const uint32_t*)&KVh[rn * LDW + kb];
                bh[nt][1] = *(const uint32_t*)&KVh[rn * LDW + kb + 8];
                bl[nt][0] = *(const uint32_t*)&KVl[rn * LDW + kb];
                bl[nt][1] = *(const uint32_t*)&KVl[rn * LDW + kb + 8];
            }
#pragma unroll
            for (int p = 0; p < 3; p++) {
#pragma unroll
                for (int mt = 0; mt < 2; mt++)
#pragma unroll
                    for (int nt = 0; nt < 8; nt++)
                        mma16816(accs[mt][nt],
                                 (p == 2) ? al[mt] : ah[mt],
                                 (p == 1) ? bl[nt] : bh[nt]);
            }
        }
        __syncthreads();   // all warps done reading K planes

        // overlap: V tile load while we do exp/split
        fillp(2, Vhi, (long)b * 128 * T_SZ + kt * 128, T_SZ);
        fillp(3, Vlo, (long)b * 128 * T_SZ + kt * 128, T_SZ);
        CPC();

        // ---- w = exp(exp(S diag-adj)), rowsum, split -> W planes ----
        float rp[2][2] = {{0.f, 0.f}, {0.f, 0.f}};
#pragma unroll
        for (int mt = 0; mt < 2; mt++)
#pragma unroll
            for (int nt = 0; nt < 8; nt++) {
                int ql = wM + mt * 16 + gID;
                int kl = wN + nt * 8 + thID * 2;
                int qi = q0 + ql, kk = kt * 128 + kl;
                float x0 = accs[mt][nt][0], x1 = accs[mt][nt][1];
                float x2 = accs[mt][nt][2], x3 = accs[mt][nt][3];
                if (qi == kk)         x0 *= cdiag;
                if (qi == kk + 1)     x1 *= cdiag;
                if (qi + 8 == kk)     x2 *= cdiag;
                if (qi + 8 == kk + 1) x3 *= cdiag;
                float w0 = __expf(__expf(x0));
                float w1 = __expf(__expf(x1));
                float w2 = __expf(__expf(x2));
                float w3 = __expf(__expf(x3));
                rp[mt][0] += w0 + w1;
                rp[mt][1] += w2 + w3;
                bf162 h2, l2;
                split2(w0, h2.x, l2.x); split2(w1, h2.y, l2.y);
                *(bf162*)&Wh[ql * LDW + kl] = h2;
                *(bf162*)&Wl[ql * LDW + kl] = l2;
                split2(w2, h2.x, l2.x); split2(w3, h2.y, l2.y);
                *(bf162*)&Wh[(ql + 8) * LDW + kl] = h2;
                *(bf162*)&Wl[(ql + 8) * LDW + kl] = l2;
            }
#pragma unroll
        for (int mt = 0; mt < 2; mt++)
#pragma unroll
            for (int h = 0; h < 2; h++) {
                float s = rp[mt][h];
                s += __shfl_xor_sync(0xffffffffu, s, 1);
                s += __shfl_xor_sync(0xffffffffu, s, 2);
                if (thID == 0)
                    rsP[(wid & 1) * 128 + wM + mt * 16 + gID + h * 8] += s;
            }
        CPW(0);
        __syncthreads();   // V ready, W visible

        // ---- AV += W V^T ----
#pragma unroll
        for (int ks = 0; ks < 8; ks++) {
            const int kb = ks * 16 + thID * 2;
            uint32_t ah[2][4], al[2][4], bh[8][2], bl[8][2];
#pragma unroll
            for (int mt = 0; mt < 2; mt++) {
                int r = wM + mt * 16 + gID;
                ah[mt][0] = *(const uint32_t*)&Wh[r * LDW + kb];
                ah[mt][1] = *(const uint32_t*)&Wh[(r + 8) * LDW + kb];
                ah[mt][2] = *(const uint32_t*)&Wh[r * LDW + kb + 8];
                ah[mt][3] = *(const uint32_t*)&Wh[(r + 8) * LDW + kb + 8];
                al[mt][0] = *(const uint32_t*)&Wl[r * LDW + kb];
                al[mt][1] = *(const uint32_t*)&Wl[(r + 8) * LDW + kb];
                al[mt][2] = *(const uint32_t*)&Wl[r * LDW + kb + 8];
                al[mt][3] = *(const uint32_t*)&Wl[(r + 8) * LDW + kb + 8];
            }
#pragma unroll
            for (int nt = 0; nt < 8; nt++) {
                int rn = wN + nt * 8 + gID;
                bh[nt][0] = *(const uint32_t*)&KVh[rn * LDW + kb];
                bh[nt][1] = *(const uint32_t*)&KVh[rn * LDW + kb + 8];
                bl[nt][0] = *(const uint32_t*)&KVl[rn * LDW + kb];
                bl[nt][1] = *(const uint32_t*)&KVl[rn * LDW + kb + 8];
            }
#pragma unroll
            for (int p = 0; p < 3; p++) {
#pragma unroll
                for (int mt = 0; mt < 2; mt++)
#pragma unroll
                    for (int nt = 0; nt < 8; nt++)
                        mma16816(accv[mt][nt],
                                 (p == 2) ? al[mt] : ah[mt],
                                 (p == 1) ? bl[nt] : bh[nt]);
            }
        }
        __syncthreads();   // done reading V planes

        if (kt + 1 < 16) {
            fillp(2, Khi, ((long)b * T_SZ + (kt + 1) * 128) * 128, 128);
            fillp(3, Klo, ((long)b * T_SZ + (kt + 1) * 128) * 128, 128);
            CPC();
            CPW(0);
            __syncthreads();
        }
    }
    __syncthreads();
    if (tid < 128) srecip[tid] = 1.0f / (rsP[tid] + rsP[128 + tid]);
    __syncthreads();

    // out[b][q][m] = AV[q][m] / rowsum[q]  (split bf16)
#pragma unroll
    for (int mt = 0; mt < 2; mt++)
#pragma unroll
        for (int nt = 0; nt < 8; nt++) {
            int i_ = wM + mt * 16 + gID;
            int j_ = wN + nt * 8 + thID * 2;
            float r0 = srecip[i_], r1 = srecip[i_ + 8];
            long base = ((long)b * T_SZ + q0 + i_) * 128 + j_;
            bf162 h2, l2;
            split2(accv[mt][nt][0] * r0, h2.x, l2.x);
            split2(accv[mt][nt][1] * r0, h2.y, l2.y);
            *(bf162*)&Ahi[base] = h2;
            *(bf162*)&Alo[base] = l2;
            split2(accv[mt][nt][2] * r1, h2.x, l2.x);
            split2(accv[mt][nt][3] * r1, h2.y, l2.y);
            *(bf162*)&Ahi[base + 8L * 128] = h2;
            *(bf162*)&Alo[base + 8L * 128] = l2;
        }
}

// ---------------------------------------------------------------------------
// Windowed branch (Tq=1 => uniform softmax => mean of value[...,33:2047]) + Wo
// ---------------------------------------------------------------------------
__global__ void __launch_bounds__(256) tail_kernel(
    const float* __restrict__ value,
    const float* __restrict__ Wo1, const float* __restrict__ bo1,
    const float* __restrict__ Wo2, const float* __restrict__ bo2,
    float* __restrict__ out)
{
    __shared__ float ex[128];
    __shared__ float hv[512];
    const int b = blockIdx.x, tid = threadIdx.x;
    const int w = tid >> 5, lane = tid & 31;

    for (int it = 0; it < 16; it++) {
        int m = it * 8 + w;
        const float* vp = value + ((long)b * M_SZ + m) * T_SZ;
        float s = 0.f;
        for (int k = 33 + lane; k < 2047; k += 32) s += vp[k];
#pragma unroll
        for (int o = 16; o; o >>= 1) s += __shfl_xor_sync(0xffffffffu, s, o);
        if (lane == 0) ex[m] = s * (1.0f / 2014.0f);
    }
    __syncthreads();
    for (int h = tid; h < 512; h += 256) {
        float s = bo1[h];
#pragma unroll 4
        for (int m = 0; m < 128; m++) s += Wo1[h * 128 + m] * ex[m];
        hv[h] = s;
    }
    __syncthreads();
    if (tid < 128) {
        float s = bo2[tid];
#pragma unroll 4
        for (int h = 0; h < 512; h++) s += Wo2[tid * 512 + h] * hv[h];
        s = s > 0.f ? s : 0.01f * s;
        out[((long)b * M_SZ + tid) * 2049 + 2048] = s;
    }
}

// ---------------------------------------------------------------------------
extern "C" void kernel_launch(void* const* d_in, const int* in_sizes, int n_in,
                              void* d_out, int out_size) {
    const int ofs = (n_in >= 15) ? 3 : 2;
    const float* pattern = (const float*)d_in[0];
    const float* value   = (const float*)d_in[1];
    const float* Wq1 = (const float*)d_in[ofs + 0];
    const float* bq1 = (const float*)d_in[ofs + 1];
    const float* Wq2 = (const float*)d_in[ofs + 2];
    const float* bq2 = (const float*)d_in[ofs + 3];
    const float* Wk1 = (const float*)d_in[ofs + 4];
    const float* bk1 = (const float*)d_in[ofs + 5];
    const float* Wk2 = (const float*)d_in[ofs + 6];
    const float* bk2 = (const float*)d_in[ofs + 7];
    const float* Wo1 = (const float*)d_in[ofs + 8];
    const float* bo1 = (const float*)d_in[ofs + 9];
    const float* Wo2 = (const float*)d_in[ofs + 10];
    const float* bo2 = (const float*)d_in[ofs + 11];
    float* out = (float*)d_out;

    bf16 *Phi, *Plo, *Hhi, *Hlo, *Qhi, *Qlo, *Khi, *Klo, *Vhi, *Vlo;
    bf16 *Athi, *Atlo, *W1h, *W1l, *W2qh, *W2ql, *W2kh, *W2kl;
    bf16 *Wo1h, *Wo1l, *Wo2h, *Wo2l;
    float* bcat;
    cudaGetSymbolAddress((void**)&Phi,  g_Phi);
    cudaGetSymbolAddress((void**)&Plo,  g_Plo);
    cudaGetSymbolAddress((void**)&Hhi,  g_Hhi);
    cudaGetSymbolAddress((void**)&Hlo,  g_Hlo);
    cudaGetSymbolAddress((void**)&Qhi,  g_Qhi);
    cudaGetSymbolAddress((void**)&Qlo,  g_Qlo);
    cudaGetSymbolAddress((void**)&Khi,  g_Khi);
    cudaGetSymbolAddress((void**)&Klo,  g_Klo);
    cudaGetSymbolAddress((void**)&Vhi,  g_Vhi);
    cudaGetSymbolAddress((void**)&Vlo,  g_Vlo);
    cudaGetSymbolAddress((void**)&Athi, g_Athi);
    cudaGetSymbolAddress((void**)&Atlo, g_Atlo);
    cudaGetSymbolAddress((void**)&W1h,  g_W1h);
    cudaGetSymbolAddress((void**)&W1l,  g_W1l);
    cudaGetSymbolAddress((void**)&W2qh, g_W2qh);
    cudaGetSymbolAddress((void**)&W2ql, g_W2ql);
    cudaGetSymbolAddress((void**)&W2kh, g_W2kh);
    cudaGetSymbolAddress((void**)&W2kl, g_W2kl);
    cudaGetSymbolAddress((void**)&Wo1h, g_Wo1h);
    cudaGetSymbolAddress((void**)&Wo1l, g_Wo1l);
    cudaGetSymbolAddress((void**)&Wo2h, g_Wo2h);
    cudaGetSymbolAddress((void**)&Wo2l, g_Wo2l);
    cudaGetSymbolAddress((void**)&bcat, g_bcat);

    cudaFuncSetAttribute(gemm_cp<0,0>, cudaFuncAttributeMaxDynamicSharedMemorySize, GEMM_SMEM);
    cudaFuncSetAttribute(gemm_cp<1,0>, cudaFuncAttributeMaxDynamicSharedMemorySize, GEMM_SMEM);
    cudaFuncSetAttribute(gemm_cp<1,1>, cudaFuncAttributeMaxDynamicSharedMemorySize, GEMM_SMEM);
    cudaFuncSetAttribute(attn_cp,      cudaFuncAttributeMaxDynamicSharedMemorySize, ATT_SMEM);

    // one-time conversions
    conv_T_split<<<dim3(64, 4, 16), 256>>>(pattern, Phi, Plo);
    conv_split<<<512, 256>>>(value, Vhi, Vlo, (long)B_SZ * 128 * T_SZ);
    conv_split<<<64, 256>>>(Wq1, W1h, W1l, 512 * 128);
    conv_split<<<64, 256>>>(Wk1, W1h + 512 * 128, W1l + 512 * 128, 512 * 128);
    conv_split<<<64, 256>>>(Wq2, W2qh, W2ql, 128 * 512);
    conv_split<<<64, 256>>>(Wk2, W2kh, W2kl, 128 * 512);
    conv_split<<<64, 256>>>(Wo1, Wo1h, Wo1l, 512 * 128);
    conv_split<<<64, 256>>>(Wo2, Wo2h, Wo2l, 128 * 512);
    bcat_kernel<<<1, 512>>>(bq1, bk1, bcat);

    const long sPM = (long)T_SZ * 128;

    // fused q+k layer-1: H[b][t][0:1024] (q half then k half)
    gemm_cp<0,0><<<dim3(16, 8, 16), 256, GEMM_SMEM>>>(
        Phi, Plo, W1h, W1l, bcat, Hhi, Hlo, nullptr,
        128, 128, sPM, 1024, (long)T_SZ * 1024);
    // layer-2 q / k
    gemm_cp<1,0><<<dim3(16, 1, 16), 256, GEMM_SMEM>>>(
        Hhi, Hlo, W2qh, W2ql, bq2, Qhi, Qlo, nullptr,
        512, 1024, (long)T_SZ * 1024, 128, sPM);
    gemm_cp<1,0><<<dim3(16, 1, 16), 256, GEMM_SMEM>>>(
        Hhi + 512, Hlo + 512, W2kh, W2kl, bk2, Khi, Klo, nullptr,
        512, 1024, (long)T_SZ * 1024, 128, sPM);
    // attention
    attn_cp<<<dim3(16, 16), 256, ATT_SMEM>>>(Qhi, Qlo, Khi, Klo, Vhi, Vlo,
                                             Athi, Atlo);
    // output MLP
    gemm_cp<0,0><<<dim3(16, 4, 16), 256, GEMM_SMEM>>>(
        Athi, Atlo, Wo1h, Wo1l, bo1, Hhi, Hlo, nullptr,
        128, 128, sPM, 512, (long)T_SZ * 512);
    gemm_cp<1,1><<<dim3(16, 1, 16), 256, GEMM_SMEM>>>(
        Hhi, Hlo, Wo2h, Wo2l, bo2, nullptr, nullptr, out,
        512, 512, (long)T_SZ * 512, 0, 0);
    // windowed branch -> out[..., 2048]
    tail_kernel<<<B_SZ, 256>>>(value, Wo1, bo1, Wo2, bo2, out);
}

// round 13
// speedup vs baseline: 2.9312x; 1.1782x over previous
#include <cuda_runtime.h>
#include <cuda_bf16.h>
#include <cuda_fp16.h>
#include <cstdint>

typedef __nv_bfloat16  bf16;
typedef __nv_bfloat162 bf162;

#define B_SZ 16
#define M_SZ 128
#define T_SZ 2048
#define H_SZ 512

// ---------------------------------------------------------------------------
// Scratch (device globals, allocation-free).
// ---------------------------------------------------------------------------
__device__ bf16 g_Phi[(size_t)B_SZ * T_SZ * 128];    // pattern [b][t][m]
__device__ bf16 g_Plo[(size_t)B_SZ * T_SZ * 128];
__device__ bf16 g_Hhi[(size_t)B_SZ * T_SZ * 1024];   // hidden [b][t][<=1024]
__device__ bf16 g_Hlo[(size_t)B_SZ * T_SZ * 1024];
__device__ bf16 g_Qhi[(size_t)B_SZ * T_SZ * 128];
__device__ bf16 g_Qlo[(size_t)B_SZ * T_SZ * 128];
__device__ bf16 g_Khi[(size_t)B_SZ * T_SZ * 128];
__device__ bf16 g_Klo[(size_t)B_SZ * T_SZ * 128];
__device__ __half g_Vh[(size_t)B_SZ * 128 * T_SZ];   // value [b][m][t] fp16
__device__ bf16 g_Athi[(size_t)B_SZ * T_SZ * 128];   // attn out [b][q][m]
__device__ bf16 g_Atlo[(size_t)B_SZ * T_SZ * 128];
__device__ bf16 g_W1h[1024 * 128],  g_W1l[1024 * 128];   // [Wq1;Wk1]
__device__ bf16 g_W2qh[128 * 512],  g_W2ql[128 * 512];
__device__ bf16 g_W2kh[128 * 512],  g_W2kl[128 * 512];
__device__ bf16 g_Wo1h[512 * 128],  g_Wo1l[512 * 128];
__device__ bf16 g_Wo2h[128 * 512],  g_Wo2l[128 * 512];
__device__ float g_bcat[1024];                            // [bq1;bk1]

// ---------------------------------------------------------------------------
// Helpers
// ---------------------------------------------------------------------------
__device__ __forceinline__ void mma16816(float* d, const uint32_t* a,
                                         const uint32_t* b) {
    asm volatile(
        "mma.sync.aligned.m16n8k16.row.col.f32.bf16.bf16.f32 "
        "{%0,%1,%2,%3}, {%4,%5,%6,%7}, {%8,%9}, {%0,%1,%2,%3};\n"
        : "+f"(d[0]), "+f"(d[1]), "+f"(d[2]), "+f"(d[3])
        : "r"(a[0]), "r"(a[1]), "r"(a[2]), "r"(a[3]), "r"(b[0]), "r"(b[1]));
}
__device__ __forceinline__ void mma16816h(float* d, const uint32_t* a,
                                          const uint32_t* b) {
    asm volatile(
        "mma.sync.aligned.m16n8k16.row.col.f32.f16.f16.f32 "
        "{%0,%1,%2,%3}, {%4,%5,%6,%7}, {%8,%9}, {%0,%1,%2,%3};\n"
        : "+f"(d[0]), "+f"(d[1]), "+f"(d[2]), "+f"(d[3])
        : "r"(a[0]), "r"(a[1]), "r"(a[2]), "r"(a[3]), "r"(b[0]), "r"(b[1]));
}
__device__ __forceinline__ void split2(float v, bf16& h, bf16& l) {
    h = __float2bfloat16(v);
    l = __float2bfloat16(v - __bfloat162float(h));
}
__device__ __forceinline__ uint32_t smem_u32(const void* p) {
    uint32_t a;
    asm("{ .reg .u64 t; cvta.to.shared.u64 t, %1; cvt.u32.u64 %0, t; }"
        : "=r"(a) : "l"(p));
    return a;
}
#define CPA16(s, g) \
    asm volatile("cp.async.cg.shared.global [%0], [%1], 16;\n" \
        :: "r"(s), "l"(g))
#define CPC() asm volatile("cp.async.commit_group;\n" ::: "memory")
#define CPW(n) asm volatile("cp.async.wait_group %0;\n" :: "n"(n) : "memory")

// ---------------------------------------------------------------------------
// Conversions (run once)
// ---------------------------------------------------------------------------
__global__ void __launch_bounds__(256) conv_T_split(const float* __restrict__ p,
                                                    bf16* __restrict__ hi,
                                                    bf16* __restrict__ lo) {
    __shared__ float s[32][33];
    const int b = blockIdx.z, t0 = blockIdx.x * 32, m0 = blockIdx.y * 32;
    const int tid = threadIdx.x;
#pragma unroll
    for (int u = 0; u < 4; u++) {
        int lin = tid + u * 256;
        int mm = lin >> 5, tt = lin & 31;
        s[mm][tt] = p[((long)b * M_SZ + m0 + mm) * T_SZ + t0 + tt];
    }
    __syncthreads();
#pragma unroll
    for (int u = 0; u < 4; u++) {
        int lin = tid + u * 256;
        int tt = lin >> 5, mm = lin & 31;
        bf16 h, l; split2(s[mm][tt], h, l);
        long o = ((long)b * T_SZ + t0 + tt) * M_SZ + m0 + mm;
        hi[o] = h; lo[o] = l;
    }
}

__global__ void conv_split(const float* __restrict__ x, bf16* __restrict__ hi,
                           bf16* __restrict__ lo, long n) {
    for (long i = (long)blockIdx.x * blockDim.x + threadIdx.x; i < n;
         i += (long)gridDim.x * blockDim.x) {
        bf16 h, l; split2(x[i], h, l);
        hi[i] = h; lo[i] = l;
    }
}

__global__ void conv_half(const float* __restrict__ x, __half* __restrict__ y,
                          long n) {
    for (long i = (long)blockIdx.x * blockDim.x + threadIdx.x; i < n;
         i += (long)gridDim.x * blockDim.x)
        y[i] = __float2half_rn(x[i]);
}

__global__ void bcat_kernel(const float* __restrict__ b0,
                            const float* __restrict__ b1,
                            float* __restrict__ dst) {
    int t = threadIdx.x;
    dst[t] = b0[t];
    dst[512 + t] = b1[t];
}

// ---------------------------------------------------------------------------
// GEMM (bf16x3 HMMA, cp.async double-buffered, 2 CTAs/SM)
//   D[i][j] = sum_k A[i][k]*W[j][k] + bias[j]
// MODE1=0: split bf16 out (Yhi/Ylo, ldY);  MODE1=1: fp32 out[(b*128+j)*2049+i]
// ---------------------------------------------------------------------------
#define LDA 40
#define GPLANE 5120
#define GSTAGE (4 * GPLANE)
#define GEMM_SMEM (2 * GSTAGE * 2 + 512)

template<int ACT, int MODE1>
__global__ void __launch_bounds__(256, 2) gemm_cp(
    const bf16* __restrict__ Ahi, const bf16* __restrict__ Alo,
    const bf16* __restrict__ Whi, const bf16* __restrict__ Wlo,
    const float* __restrict__ bias,
    bf16* __restrict__ Yhi, bf16* __restrict__ Ylo, float* __restrict__ Yf,
    int K, int ldA, long strideA, int ldY, long strideY)
{
    extern __shared__ __align__(16) char smem[];
    bf16* S = (bf16*)smem;
    float* sbias = (float*)(smem + 2 * GSTAGE * 2);
    const uint32_t sb = smem_u32(smem);
    const int tid = threadIdx.x, lane = tid & 31, wid = tid >> 5;
    const int gID = lane >> 2, thID = lane & 3;
    const int b = blockIdx.z, i0 = blockIdx.x * 128, j0 = blockIdx.y * 128;
    const int wM = (wid >> 1) * 32, wN = (wid & 1) * 64;

    if (tid < 128) sbias[tid] = bias[j0 + tid];

    const bf16* Abh = Ahi + (long)b * strideA + (long)i0 * ldA;
    const bf16* Abl = Alo + (long)b * strideA + (long)i0 * ldA;
    const bf16* Wbh = Whi + (long)j0 * K;
    const bf16* Wbl = Wlo + (long)j0 * K;

    float acc[2][8][4];
#pragma unroll
    for (int mt = 0; mt < 2; mt++)
#pragma unroll
        for (int nt = 0; nt < 8; nt++)
#pragma unroll
            for (int e = 0; e < 4; e++) acc[mt][nt][e] = 0.f;

    const int nch = K >> 5;

    auto fill = [&](int st, int k0) {
        const bf16* srcs[4] = {Abh, Abl, Wbh, Wbl};
        const int lds[4] = {ldA, ldA, K, K};
#pragma unroll
        for (int p = 0; p < 4; p++) {
#pragma unroll
            for (int u = 0; u < 2; u++) {
                int c = tid + u * 256;
                int r = c >> 2, off = (c & 3) * 16;
                uint32_t sa = sb + (st * GSTAGE + p * GPLANE + r * LDA) * 2 + off;
                const char* ga = (const char*)(srcs[p] + (long)r * lds[p] + k0) + off;
                CPA16(sa, ga);
            }
        }
    };

    fill(0, 0); CPC();
    for (int ch = 0; ch < nch; ch++) {
        if (ch + 1 < nch) fill((ch + 1) & 1, (ch + 1) * 32);
        CPC();
        CPW(1);
        __syncthreads();
        const int st = ch & 1;
        bf16* Ah = S + st * GSTAGE;
        bf16* Al = Ah + GPLANE;
        bf16* Bh = Al + GPLANE;
        bf16* Bl = Bh + GPLANE;
#pragma unroll
        for (int ks = 0; ks < 2; ks++) {
            const int kb = ks * 16 + thID * 2;
            uint32_t ah[2][4], al[2][4];
#pragma unroll
            for (int mt = 0; mt < 2; mt++) {
                int r = wM + mt * 16 + gID;
                ah[mt][0] = *(const uint32_t*)&Ah[r * LDA + kb];
                ah[mt][1] = *(const uint32_t*)&Ah[(r + 8) * LDA + kb];
                ah[mt][2] = *(const uint32_t*)&Ah[r * LDA + kb + 8];
                ah[mt][3] = *(const uint32_t*)&Ah[(r + 8) * LDA + kb + 8];
                al[mt][0] = *(const uint32_t*)&Al[r * LDA + kb];
                al[mt][1] = *(const uint32_t*)&Al[(r + 8) * LDA + kb];
                al[mt][2] = *(const uint32_t*)&Al[r * LDA + kb + 8];
                al[mt][3] = *(const uint32_t*)&Al[(r + 8) * LDA + kb + 8];
            }
            // two n-halves: fewer live b-frags -> <=128 regs for 2 CTAs/SM
#pragma unroll
            for (int nh = 0; nh < 2; nh++) {
                uint32_t bh[4][2], bl[4][2];
#pragma unroll
                for (int j = 0; j < 4; j++) {
                    int rn = wN + (nh * 4 + j) * 8 + gID;
                    bh[j][0] = *(const uint32_t*)&Bh[rn * LDA + kb];
                    bh[j][1] = *(const uint32_t*)&Bh[rn * LDA + kb + 8];
                    bl[j][0] = *(const uint32_t*)&Bl[rn * LDA + kb];
                    bl[j][1] = *(const uint32_t*)&Bl[rn * LDA + kb + 8];
                }
#pragma unroll
                for (int p = 0; p < 3; p++)
#pragma unroll
                    for (int mt = 0; mt < 2; mt++)
#pragma unroll
                        for (int j = 0; j < 4; j++)
                            mma16816(acc[mt][nh * 4 + j],
                                     (p == 2) ? al[mt] : ah[mt],
                                     (p == 1) ? bl[j] : bh[j]);
            }
        }
        __syncthreads();
    }

    // epilogue
#pragma unroll
    for (int mt = 0; mt < 2; mt++)
#pragma unroll
        for (int nt = 0; nt < 8; nt++) {
            int i_ = wM + mt * 16 + gID;
            int j_ = wN + nt * 8 + thID * 2;
            float v0 = acc[mt][nt][0] + sbias[j_];
            float v1 = acc[mt][nt][1] + sbias[j_ + 1];
            float v2 = acc[mt][nt][2] + sbias[j_];
            float v3 = acc[mt][nt][3] + sbias[j_ + 1];
            if (ACT) {
                v0 = v0 > 0.f ? v0 : 0.01f * v0;
                v1 = v1 > 0.f ? v1 : 0.01f * v1;
                v2 = v2 > 0.f ? v2 : 0.01f * v2;
                v3 = v3 > 0.f ? v3 : 0.01f * v3;
            }
            if (!MODE1) {
                long base = (long)b * strideY + (long)(i0 + i_) * ldY + j0 + j_;
                bf162 h2, l2;
                split2(v0, h2.x, l2.x); split2(v1, h2.y, l2.y);
                *(bf162*)&Yhi[base] = h2;
                *(bf162*)&Ylo[base] = l2;
                split2(v2, h2.x, l2.x); split2(v3, h2.y, l2.y);
                *(bf162*)&Yhi[base + 8L * ldY] = h2;
                *(bf162*)&Ylo[base + 8L * ldY] = l2;
            } else {
                long c0 = ((long)b * 128 + j0 + j_) * 2049 + i0 + i_;
                Yf[c0] = v0;
                Yf[c0 + 2049] = v1;
                Yf[c0 + 8] = v2;
                Yf[c0 + 2049 + 8] = v3;
            }
        }
}

// ---------------------------------------------------------------------------
// Fused attention: S in bf16x3, AV in single fp16 (w in [1.7,6.2], v ~N(0,1)).
// Planes: Qh,Ql,Kh,Kl (bf16), V (fp16), W (fp16). K/V prefetch fully hidden.
// ---------------------------------------------------------------------------
#define LDW 136
#define APL (128 * LDW * 2)                 // bytes per plane
#define ATT_SMEM (6 * APL + 256 * 4 + 128 * 4)

__global__ void __launch_bounds__(256, 1) attn_cp(
    const bf16* __restrict__ Qhi, const bf16* __restrict__ Qlo,
    const bf16* __restrict__ Khi, const bf16* __restrict__ Klo,
    const __half* __restrict__ Vg,
    bf16* __restrict__ Ahi, bf16* __restrict__ Alo)
{
    extern __shared__ __align__(16) char smem[];
    bf16*   Qh = (bf16*)(smem);
    bf16*   Ql = (bf16*)(smem + APL);
    bf16*   Kh = (bf16*)(smem + 2 * APL);
    bf16*   Kl = (bf16*)(smem + 3 * APL);
    __half* Vp = (__half*)(smem + 4 * APL);
    __half* Wp = (__half*)(smem + 5 * APL);
    float* rsP    = (float*)(smem + 6 * APL);   // [2][128]
    float* srecip = rsP + 256;
    const uint32_t sb = smem_u32(smem);

    const int tid = threadIdx.x, lane = tid & 31, wid = tid >> 5;
    const int gID = lane >> 2, thID = lane & 3;
    const int b = blockIdx.y, q0 = blockIdx.x * 128;
    const int wM = (wid >> 1) * 32, wN = (wid & 1) * 64;
    const float cdiag = 0.97790291308792045f;  // 1 - 1/sqrt(2048)

    // async-copy one 128x128 (2B elem) plane
    auto fillp = [&](uint32_t byteoff, const void* src, long base, int ld) {
#pragma unroll
        for (int u = 0; u < 8; u++) {
            int c = tid + u * 256;
            int r = c >> 4, off = (c & 15) * 16;
            uint32_t sa = sb + byteoff + (r * LDW) * 2 + off;
            const char* ga = (const char*)src + (base + (long)r * ld) * 2 + off;
            CPA16(sa, ga);
        }
    };

    const long qbase = ((long)b * T_SZ + q0) * 128;
    const long kstr  = (long)b * T_SZ * 128;
    const long vstr  = (long)b * 128 * T_SZ;
    fillp(0,       Qhi, qbase, 128);
    fillp(APL,     Qlo, qbase, 128);
    fillp(2 * APL, Khi, kstr, 128);
    fillp(3 * APL, Klo, kstr, 128);
    fillp(4 * APL, Vg,  vstr, T_SZ);
    CPC();
    if (tid < 256) rsP[tid] = 0.f;

    float accv[2][8][4];
#pragma unroll
    for (int mt = 0; mt < 2; mt++)
#pragma unroll
        for (int nt = 0; nt < 8; nt++)
#pragma unroll
            for (int e = 0; e < 4; e++) accv[mt][nt][e] = 0.f;

    CPW(0);
    __syncthreads();

    for (int kt = 0; kt < 16; kt++) {
        // ---- S = Q K^T (bf16x3) ----
        float accs[2][8][4];
#pragma unroll
        for (int mt = 0; mt < 2; mt++)
#pragma unroll
            for (int nt = 0; nt < 8; nt++)
#pragma unroll
                for (int e = 0; e < 4; e++) accs[mt][nt][e] = 0.f;
#pragma unroll
        for (int ks = 0; ks < 8; ks++) {
            const int kb = ks * 16 + thID * 2;
            uint32_t ah[2][4], al[2][4], bh[8][2], bl[8][2];
#pragma unroll
            for (int mt = 0; mt < 2; mt++) {
                int r = wM + mt * 16 + gID;
                ah[mt][0] = *(const uint32_t*)&Qh[r * LDW + kb];
                ah[mt][1] = *(const uint32_t*)&Qh[(r + 8) * LDW + kb];
                ah[mt][2] = *(const uint32_t*)&Qh[r * LDW + kb + 8];
                ah[mt][3] = *(const uint32_t*)&Qh[(r + 8) * LDW + kb + 8];
                al[mt][0] = *(const uint32_t*)&Ql[r * LDW + kb];
                al[mt][1] = *(const uint32_t*)&Ql[(r + 8) * LDW + kb];
                al[mt][2] = *(const uint32_t*)&Ql[r * LDW + kb + 8];
                al[mt][3] = *(const uint32_t*)&Ql[(r + 8) * LDW + kb + 8];
            }
#pragma unroll
            for (int nt = 0; nt < 8; nt++) {
                int rn = wN + nt * 8 + gID;
                bh[nt][0] = *(const uint32_t*)&Kh[rn * LDW + kb];
                bh[nt][1] = *(const uint32_t*)&Kh[rn * LDW + kb + 8];
                bl[nt][0] = *(const uint32_t*)&Kl[rn * LDW + kb];
                bl[nt][1] = *(const uint32_t*)&Kl[rn * LDW + kb + 8];
            }
#pragma unroll
            for (int p = 0; p < 3; p++)
#pragma unroll
                for (int mt = 0; mt < 2; mt++)
#pragma unroll
                    for (int nt = 0; nt < 8; nt++)
                        mma16816(accs[mt][nt],
                                 (p == 2) ? al[mt] : ah[mt],
                                 (p == 1) ? bl[nt] : bh[nt]);
        }
        __syncthreads();   // K planes free

        // prefetch K(kt+1): hidden under exp + AV
        if (kt + 1 < 16) {
            fillp(2 * APL, Khi, kstr + (long)(kt + 1) * 128 * 128, 128);
            fillp(3 * APL, Klo, kstr + (long)(kt + 1) * 128 * 128, 128);
            CPC();
        }

        // ---- w = exp(exp(S diag-adj)) -> fp16 W plane, fp32 rowsum ----
        float rp[2][2] = {{0.f, 0.f}, {0.f, 0.f}};
#pragma unroll
        for (int mt = 0; mt < 2; mt++)
#pragma unroll
            for (int nt = 0; nt < 8; nt++) {
                int ql = wM + mt * 16 + gID;
                int kl = wN + nt * 8 + thID * 2;
                int qi = q0 + ql, kk = kt * 128 + kl;
                float x0 = accs[mt][nt][0], x1 = accs[mt][nt][1];
                float x2 = accs[mt][nt][2], x3 = accs[mt][nt][3];
                if (qi == kk)         x0 *= cdiag;
                if (qi == kk + 1)     x1 *= cdiag;
                if (qi + 8 == kk)     x2 *= cdiag;
                if (qi + 8 == kk + 1) x3 *= cdiag;
                float w0 = __expf(__expf(x0));
                float w1 = __expf(__expf(x1));
                float w2 = __expf(__expf(x2));
                float w3 = __expf(__expf(x3));
                rp[mt][0] += w0 + w1;
                rp[mt][1] += w2 + w3;
                *(__half2*)&Wp[ql * LDW + kl] =
                    __float22half2_rn(make_float2(w0, w1));
                *(__half2*)&Wp[(ql + 8) * LDW + kl] =
                    __float22half2_rn(make_float2(w2, w3));
            }
#pragma unroll
        for (int mt = 0; mt < 2; mt++)
#pragma unroll
            for (int h = 0; h < 2; h++) {
                float s = rp[mt][h];
                s += __shfl_xor_sync(0xffffffffu, s, 1);
                s += __shfl_xor_sync(0xffffffffu, s, 2);
                if (thID == 0)
                    rsP[(wid & 1) * 128 + wM + mt * 16 + gID + h * 8] += s;
            }
        if (kt == 15) { CPW(0); } else { CPW(1); }   // V(kt) ready
        __syncthreads();                              // W visible, V ready

        // ---- AV += W V^T (single fp16 product) ----
#pragma unroll
        for (int ks = 0; ks < 8; ks++) {
            const int kb = ks * 16 + thID * 2;
            uint32_t ah[2][4], bh[8][2];
#pragma unroll
            for (int mt = 0; mt < 2; mt++) {
                int r = wM + mt * 16 + gID;
                ah[mt][0] = *(const uint32_t*)&Wp[r * LDW + kb];
                ah[mt][1] = *(const uint32_t*)&Wp[(r + 8) * LDW + kb];
                ah[mt][2] = *(const uint32_t*)&Wp[r * LDW + kb + 8];
                ah[mt][3] = *(const uint32_t*)&Wp[(r + 8) * LDW + kb + 8];
            }
#pragma unroll
            for (int nt = 0; nt < 8; nt++) {
                int rn = wN + nt * 8 + gID;
                bh[nt][0] = *(const uint32_t*)&Vp[rn * LDW + kb];
                bh[nt][1] = *(const uint32_t*)&Vp[rn * LDW + kb + 8];
            }
#pragma unroll
            for (int mt = 0; mt < 2; mt++)
#pragma unroll
                for (int nt = 0; nt < 8; nt++)
                    mma16816h(accv[mt][nt], ah[mt], bh[nt]);
        }
        __syncthreads();   // V plane free

        if (kt + 1 < 16) {
            fillp(4 * APL, Vg, vstr + (long)(kt + 1) * 128, T_SZ);
            CPC();
            CPW(1);          // K(kt+1) done (V(kt+1) may stay in flight)
            __syncthreads();
        }
    }
    __syncthreads();
    if (tid < 128) srecip[tid] = 1.0f / (rsP[tid] + rsP[128 + tid]);
    __syncthreads();

    // out[b][q][m] = AV[q][m] / rowsum[q]  (split bf16)
#pragma unroll
    for (int mt = 0; mt < 2; mt++)
#pragma unroll
        for (int nt = 0; nt < 8; nt++) {
            int i_ = wM + mt * 16 + gID;
            int j_ = wN + nt * 8 + thID * 2;
            float r0 = srecip[i_], r1 = srecip[i_ + 8];
            long base = ((long)b * T_SZ + q0 + i_) * 128 + j_;
            bf162 h2, l2;
            split2(accv[mt][nt][0] * r0, h2.x, l2.x);
            split2(accv[mt][nt][1] * r0, h2.y, l2.y);
            *(bf162*)&Ahi[base] = h2;
            *(bf162*)&Alo[base] = l2;
            split2(accv[mt][nt][2] * r1, h2.x, l2.x);
            split2(accv[mt][nt][3] * r1, h2.y, l2.y);
            *(bf162*)&Ahi[base + 8L * 128] = h2;
            *(bf162*)&Alo[base + 8L * 128] = l2;
        }
}

// ---------------------------------------------------------------------------
// Windowed branch (Tq=1 => uniform softmax => mean of value[...,33:2047]) + Wo
// ---------------------------------------------------------------------------
__global__ void __launch_bounds__(256) tail_kernel(
    const float* __restrict__ value,
    const float* __restrict__ Wo1, const float* __restrict__ bo1,
    const float* __restrict__ Wo2, const float* __restrict__ bo2,
    float* __restrict__ out)
{
    __shared__ float ex[128];
    __shared__ float hv[512];
    const int b = blockIdx.x, tid = threadIdx.x;
    const int w = tid >> 5, lane = tid & 31;

    for (int it = 0; it < 16; it++) {
        int m = it * 8 + w;
        const float* vp = value + ((long)b * M_SZ + m) * T_SZ;
        float s = 0.f;
        for (int k = 33 + lane; k < 2047; k += 32) s += vp[k];
#pragma unroll
        for (int o = 16; o; o >>= 1) s += __shfl_xor_sync(0xffffffffu, s, o);
        if (lane == 0) ex[m] = s * (1.0f / 2014.0f);
    }
    __syncthreads();
    for (int h = tid; h < 512; h += 256) {
        float s = bo1[h];
#pragma unroll 4
        for (int m = 0; m < 128; m++) s += Wo1[h * 128 + m] * ex[m];
        hv[h] = s;
    }
    __syncthreads();
    if (tid < 128) {
        float s = bo2[tid];
#pragma unroll 4
        for (int h = 0; h < 512; h++) s += Wo2[tid * 512 + h] * hv[h];
        s = s > 0.f ? s : 0.01f * s;
        out[((long)b * M_SZ + tid) * 2049 + 2048] = s;
    }
}

// ---------------------------------------------------------------------------
extern "C" void kernel_launch(void* const* d_in, const int* in_sizes, int n_in,
                              void* d_out, int out_size) {
    const int ofs = (n_in >= 15) ? 3 : 2;
    const float* pattern = (const float*)d_in[0];
    const float* value   = (const float*)d_in[1];
    const float* Wq1 = (const float*)d_in[ofs + 0];
    const float* bq1 = (const float*)d_in[ofs + 1];
    const float* Wq2 = (const float*)d_in[ofs + 2];
    const float* bq2 = (const float*)d_in[ofs + 3];
    const float* Wk1 = (const float*)d_in[ofs + 4];
    const float* bk1 = (const float*)d_in[ofs + 5];
    const float* Wk2 = (const float*)d_in[ofs + 6];
    const float* bk2 = (const float*)d_in[ofs + 7];
    const float* Wo1 = (const float*)d_in[ofs + 8];
    const float* bo1 = (const float*)d_in[ofs + 9];
    const float* Wo2 = (const float*)d_in[ofs + 10];
    const float* bo2 = (const float*)d_in[ofs + 11];
    float* out = (float*)d_out;

    bf16 *Phi, *Plo, *Hhi, *Hlo, *Qhi, *Qlo, *Khi, *Klo;
    bf16 *Athi, *Atlo, *W1h, *W1l, *W2qh, *W2ql, *W2kh, *W2kl;
    bf16 *Wo1h, *Wo1l, *Wo2h, *Wo2l;
    __half* Vh;
    float* bcat;
    cudaGetSymbolAddress((void**)&Phi,  g_Phi);
    cudaGetSymbolAddress((void**)&Plo,  g_Plo);
    cudaGetSymbolAddress((void**)&Hhi,  g_Hhi);
    cudaGetSymbolAddress((void**)&Hlo,  g_Hlo);
    cudaGetSymbolAddress((void**)&Qhi,  g_Qhi);
    cudaGetSymbolAddress((void**)&Qlo,  g_Qlo);
    cudaGetSymbolAddress((void**)&Khi,  g_Khi);
    cudaGetSymbolAddress((void**)&Klo,  g_Klo);
    cudaGetSymbolAddress((void**)&Vh,   g_Vh);
    cudaGetSymbolAddress((void**)&Athi, g_Athi);
    cudaGetSymbolAddress((void**)&Atlo, g_Atlo);
    cudaGetSymbolAddress((void**)&W1h,  g_W1h);
    cudaGetSymbolAddress((void**)&W1l,  g_W1l);
    cudaGetSymbolAddress((void**)&W2qh, g_W2qh);
    cudaGetSymbolAddress((void**)&W2ql, g_W2ql);
    cudaGetSymbolAddress((void**)&W2kh, g_W2kh);
    cudaGetSymbolAddress((void**)&W2kl, g_W2kl);
    cudaGetSymbolAddress((void**)&Wo1h, g_Wo1h);
    cudaGetSymbolAddress((void**)&Wo1l, g_Wo1l);
    cudaGetSymbolAddress((void**)&Wo2h, g_Wo2h);
    cudaGetSymbolAddress((void**)&Wo2l, g_Wo2l);
    cudaGetSymbolAddress((void**)&bcat, g_bcat);

    cudaFuncSetAttribute(gemm_cp<0,0>, cudaFuncAttributeMaxDynamicSharedMemorySize, GEMM_SMEM);
    cudaFuncSetAttribute(gemm_cp<1,0>, cudaFuncAttributeMaxDynamicSharedMemorySize, GEMM_SMEM);
    cudaFuncSetAttribute(gemm_cp<1,1>, cudaFuncAttributeMaxDynamicSharedMemorySize, GEMM_SMEM);
    cudaFuncSetAttribute(attn_cp,      cudaFuncAttributeMaxDynamicSharedMemorySize, ATT_SMEM);

    // one-time conversions
    conv_T_split<<<dim3(64, 4, 16), 256>>>(pattern, Phi, Plo);
    conv_half<<<512, 256>>>(value, Vh, (long)B_SZ * 128 * T_SZ);
    conv_split<<<64, 256>>>(Wq1, W1h, W1l, 512 * 128);
    conv_split<<<64, 256>>>(Wk1, W1h + 512 * 128, W1l + 512 * 128, 512 * 128);
    conv_split<<<64, 256>>>(Wq2, W2qh, W2ql, 128 * 512);
    conv_split<<<64, 256>>>(Wk2, W2kh, W2kl, 128 * 512);
    conv_split<<<64, 256>>>(Wo1, Wo1h, Wo1l, 512 * 128);
    conv_split<<<64, 256>>>(Wo2, Wo2h, Wo2l, 128 * 512);
    bcat_kernel<<<1, 512>>>(bq1, bk1, bcat);

    const long sPM = (long)T_SZ * 128;

    // fused q+k layer-1: H[b][t][0:1024] (q half then k half)
    gemm_cp<0,0><<<dim3(16, 8, 16), 256, GEMM_SMEM>>>(
        Phi, Plo, W1h, W1l, bcat, Hhi, Hlo, nullptr,
        128, 128, sPM, 1024, (long)T_SZ * 1024);
    // layer-2 q / k
    gemm_cp<1,0><<<dim3(16, 1, 16), 256, GEMM_SMEM>>>(
        Hhi, Hlo, W2qh, W2ql, bq2, Qhi, Qlo, nullptr,
        512, 1024, (long)T_SZ * 1024, 128, sPM);
    gemm_cp<1,0><<<dim3(16, 1, 16), 256, GEMM_SMEM>>>(
        Hhi + 512, Hlo + 512, W2kh, W2kl, bk2, Khi, Klo, nullptr,
        512, 1024, (long)T_SZ * 1024, 128, sPM);
    // attention
    attn_cp<<<dim3(16, 16), 256, ATT_SMEM>>>(Qhi, Qlo, Khi, Klo, Vh,
                                             Athi, Atlo);
    // output MLP
    gemm_cp<0,0><<<dim3(16, 4, 16), 256, GEMM_SMEM>>>(
        Athi, Atlo, Wo1h, Wo1l, bo1, Hhi, Hlo, nullptr,
        128, 128, sPM, 512, (long)T_SZ * 512);
    gemm_cp<1,1><<<dim3(16, 1, 16), 256, GEMM_SMEM>>>(
        Hhi, Hlo, Wo2h, Wo2l, bo2, nullptr, nullptr, out,
        512, 512, (long)T_SZ * 512, 0, 0);
    // windowed branch -> out[..., 2048]
    tail_kernel<<<B_SZ, 256>>>(value, Wo1, bo1, Wo2, bo2, out);
}

// round 17
// speedup vs baseline: 3.3579x; 1.1456x over previous
#include <cuda_runtime.h>
#include <cuda_bf16.h>
#include <cuda_fp16.h>
#include <cstdint>

typedef __nv_bfloat16  bf16;
typedef __nv_bfloat162 bf162;

#define B_SZ 16
#define M_SZ 128
#define T_SZ 2048
#define H_SZ 512

// ---------------------------------------------------------------------------
// Scratch (device globals, allocation-free).
// ---------------------------------------------------------------------------
__device__ bf16 g_Phi[(size_t)B_SZ * T_SZ * 128];    // pattern [b][t][m]
__device__ bf16 g_Plo[(size_t)B_SZ * T_SZ * 128];
__device__ bf16 g_Hhi[(size_t)B_SZ * T_SZ * 1024];   // hidden [b][t][<=1024]
__device__ bf16 g_Hlo[(size_t)B_SZ * T_SZ * 1024];
__device__ __half g_QK[(size_t)B_SZ * T_SZ * 256];   // [b][t][q(128);k(128)] fp16
__device__ __half g_Vh[(size_t)B_SZ * 128 * T_SZ];   // value [b][m][t] fp16
__device__ bf16 g_Athi[(size_t)B_SZ * T_SZ * 128];   // attn out [b][q][m]
__device__ bf16 g_Atlo[(size_t)B_SZ * T_SZ * 128];
__device__ bf16 g_W1h[1024 * 128],  g_W1l[1024 * 128];   // [Wq1;Wk1]
__device__ bf16 g_W2h[256 * 512],   g_W2l[256 * 512];    // [Wq2;Wk2]
__device__ bf16 g_Wo1h[512 * 128],  g_Wo1l[512 * 128];
__device__ bf16 g_Wo2h[128 * 512],  g_Wo2l[128 * 512];
__device__ float g_bcat1[1024];                           // [bq1;bk1]
__device__ float g_bcat2[256];                            // [bq2;bk2]

// ---------------------------------------------------------------------------
// Helpers
// ---------------------------------------------------------------------------
__device__ __forceinline__ void mma16816(float* d, const uint32_t* a,
                                         const uint32_t* b) {
    asm volatile(
        "mma.sync.aligned.m16n8k16.row.col.f32.bf16.bf16.f32 "
        "{%0,%1,%2,%3}, {%4,%5,%6,%7}, {%8,%9}, {%0,%1,%2,%3};\n"
        : "+f"(d[0]), "+f"(d[1]), "+f"(d[2]), "+f"(d[3])
        : "r"(a[0]), "r"(a[1]), "r"(a[2]), "r"(a[3]), "r"(b[0]), "r"(b[1]));
}
__device__ __forceinline__ void mma16816h(float* d, const uint32_t* a,
                                          const uint32_t* b) {
    asm volatile(
        "mma.sync.aligned.m16n8k16.row.col.f32.f16.f16.f32 "
        "{%0,%1,%2,%3}, {%4,%5,%6,%7}, {%8,%9}, {%0,%1,%2,%3};\n"
        : "+f"(d[0]), "+f"(d[1]), "+f"(d[2]), "+f"(d[3])
        : "r"(a[0]), "r"(a[1]), "r"(a[2]), "r"(a[3]), "r"(b[0]), "r"(b[1]));
}
__device__ __forceinline__ void split2(float v, bf16& h, bf16& l) {
    h = __float2bfloat16(v);
    l = __float2bfloat16(v - __bfloat162float(h));
}
__device__ __forceinline__ uint32_t smem_u32(const void* p) {
    uint32_t a;
    asm("{ .reg .u64 t; cvta.to.shared.u64 t, %1; cvt.u32.u64 %0, t; }"
        : "=r"(a) : "l"(p));
    return a;
}
#define CPA16(s, g) \
    asm volatile("cp.async.cg.shared.global [%0], [%1], 16;\n" \
        :: "r"(s), "l"(g))
#define CPC() asm volatile("cp.async.commit_group;\n" ::: "memory")
#define CPW(n) asm volatile("cp.async.wait_group %0;\n" :: "n"(n) : "memory")

// ---------------------------------------------------------------------------
// Conversions (3 launches total)
// ---------------------------------------------------------------------------
__global__ void __launch_bounds__(256) conv_T_split(const float* __restrict__ p,
                                                    bf16* __restrict__ hi,
                                                    bf16* __restrict__ lo) {
    __shared__ float s[32][33];
    const int b = blockIdx.z, t0 = blockIdx.x * 32, m0 = blockIdx.y * 32;
    const int tid = threadIdx.x;
#pragma unroll
    for (int u = 0; u < 4; u++) {
        int lin = tid + u * 256;
        int mm = lin >> 5, tt = lin & 31;
        s[mm][tt] = p[((long)b * M_SZ + m0 + mm) * T_SZ + t0 + tt];
    }
    __syncthreads();
#pragma unroll
    for (int u = 0; u < 4; u++) {
        int lin = tid + u * 256;
        int tt = lin >> 5, mm = lin & 31;
        bf16 h, l; split2(s[mm][tt], h, l);
        long o = ((long)b * T_SZ + t0 + tt) * M_SZ + m0 + mm;
        hi[o] = h; lo[o] = l;
    }
}

__global__ void conv_half(const float* __restrict__ x, __half* __restrict__ y,
                          long n) {
    for (long i = (long)blockIdx.x * blockDim.x + threadIdx.x; i < n;
         i += (long)gridDim.x * blockDim.x)
        y[i] = __float2half_rn(x[i]);
}

// all 6 weight splits + both bias concats in one kernel
__global__ void conv_weights(
    const float* __restrict__ Wq1, const float* __restrict__ Wk1,
    const float* __restrict__ Wq2, const float* __restrict__ Wk2,
    const float* __restrict__ Wo1, const float* __restrict__ Wo2,
    const float* __restrict__ bq1, const float* __restrict__ bk1,
    const float* __restrict__ bq2, const float* __restrict__ bk2,
    bf16* __restrict__ W1h, bf16* __restrict__ W1l,
    bf16* __restrict__ W2h, bf16* __restrict__ W2l,
    bf16* __restrict__ Wo1h, bf16* __restrict__ Wo1l,
    bf16* __restrict__ Wo2h, bf16* __restrict__ Wo2l,
    float* __restrict__ bc1, float* __restrict__ bc2)
{
    const long gid = (long)blockIdx.x * blockDim.x + threadIdx.x;
    const long stride = (long)gridDim.x * blockDim.x;
    for (long i = gid; i < 65536; i += stride) {
        bf16 h, l;
        split2(Wq1[i], h, l); W1h[i] = h;          W1l[i] = l;
        split2(Wk1[i], h, l); W1h[65536 + i] = h;  W1l[65536 + i] = l;
        split2(Wq2[i], h, l); W2h[i] = h;          W2l[i] = l;
        split2(Wk2[i], h, l); W2h[65536 + i] = h;  W2l[65536 + i] = l;
        split2(Wo1[i], h, l); Wo1h[i] = h;         Wo1l[i] = l;
        split2(Wo2[i], h, l); Wo2h[i] = h;         Wo2l[i] = l;
    }
    for (long i = gid; i < 512; i += stride) {
        bc1[i] = bq1[i]; bc1[512 + i] = bk1[i];
    }
    for (long i = gid; i < 128; i += stride) {
        bc2[i] = bq2[i]; bc2[128 + i] = bk2[i];
    }
}

// ---------------------------------------------------------------------------
// GEMM (bf16x3 HMMA, cp.async double-buffered, 2 CTAs/SM)
//   D[i][j] = sum_k A[i][k + by*aYOff]*W[j][k] + bias[j]
// aYOff: per-j-block column offset into A (merged q/k layer-2 uses 512).
// MODE 0: split bf16 out (Yhi/Ylo, ldY)
// MODE 1: fp32 out[(b*128+j)*2049+i]
// MODE 2: fp16 out (Yh, ldY)
// ---------------------------------------------------------------------------
#define LDA 40
#define GPLANE 5120
#define GSTAGE (4 * GPLANE)
#define GEMM_SMEM (2 * GSTAGE * 2 + 512)

template<int ACT, int MODE>
__global__ void __launch_bounds__(256, 2) gemm_cp(
    const bf16* __restrict__ Ahi, const bf16* __restrict__ Alo,
    const bf16* __restrict__ Whi, const bf16* __restrict__ Wlo,
    const float* __restrict__ bias,
    bf16* __restrict__ Yhi, bf16* __restrict__ Ylo, float* __restrict__ Yf,
    __half* __restrict__ Yh,
    int K, int ldA, long strideA, int ldY, long strideY, int aYOff)
{
    extern __shared__ __align__(16) char smem[];
    bf16* S = (bf16*)smem;
    float* sbias = (float*)(smem + 2 * GSTAGE * 2);
    const uint32_t sb = smem_u32(smem);
    const int tid = threadIdx.x, lane = tid & 31, wid = tid >> 5;
    const int gID = lane >> 2, thID = lane & 3;
    const int b = blockIdx.z, i0 = blockIdx.x * 128, j0 = blockIdx.y * 128;
    const int wM = (wid >> 1) * 32, wN = (wid & 1) * 64;

    if (tid < 128) sbias[tid] = bias[j0 + tid];

    const long aoff = (long)blockIdx.y * aYOff;   // q/k half select (merged L2)
    const bf16* Abh = Ahi + (long)b * strideA + (long)i0 * ldA + aoff;
    const bf16* Abl = Alo + (long)b * strideA + (long)i0 * ldA + aoff;
    const bf16* Wbh = Whi + (long)j0 * K;
    const bf16* Wbl = Wlo + (long)j0 * K;

    float acc[2][8][4];
#pragma unroll
    for (int mt = 0; mt < 2; mt++)
#pragma unroll
        for (int nt = 0; nt < 8; nt++)
#pragma unroll
            for (int e = 0; e < 4; e++) acc[mt][nt][e] = 0.f;

    const int nch = K >> 5;

    auto fill = [&](int st, int k0) {
        const bf16* srcs[4] = {Abh, Abl, Wbh, Wbl};
        const int lds[4] = {ldA, ldA, K, K};
#pragma unroll
        for (int p = 0; p < 4; p++) {
#pragma unroll
            for (int u = 0; u < 2; u++) {
                int c = tid + u * 256;
                int r = c >> 2, off = (c & 3) * 16;
                uint32_t sa = sb + (st * GSTAGE + p * GPLANE + r * LDA) * 2 + off;
                const char* ga = (const char*)(srcs[p] + (long)r * lds[p] + k0) + off;
                CPA16(sa, ga);
            }
        }
    };

    fill(0, 0); CPC();
    for (int ch = 0; ch < nch; ch++) {
        if (ch + 1 < nch) fill((ch + 1) & 1, (ch + 1) * 32);
        CPC();
        CPW(1);
        __syncthreads();
        const int st = ch & 1;
        bf16* Ah = S + st * GSTAGE;
        bf16* Al = Ah + GPLANE;
        bf16* Bh = Al + GPLANE;
        bf16* Bl = Bh + GPLANE;
#pragma unroll
        for (int ks = 0; ks < 2; ks++) {
            const int kb = ks * 16 + thID * 2;
            uint32_t ah[2][4], al[2][4];
#pragma unroll
            for (int mt = 0; mt < 2; mt++) {
                int r = wM + mt * 16 + gID;
                ah[mt][0] = *(const uint32_t*)&Ah[r * LDA + kb];
                ah[mt][1] = *(const uint32_t*)&Ah[(r + 8) * LDA + kb];
                ah[mt][2] = *(const uint32_t*)&Ah[r * LDA + kb + 8];
                ah[mt][3] = *(const uint32_t*)&Ah[(r + 8) * LDA + kb + 8];
                al[mt][0] = *(const uint32_t*)&Al[r * LDA + kb];
                al[mt][1] = *(const uint32_t*)&Al[(r + 8) * LDA + kb];
                al[mt][2] = *(const uint32_t*)&Al[r * LDA + kb + 8];
                al[mt][3] = *(const uint32_t*)&Al[(r + 8) * LDA + kb + 8];
            }
#pragma unroll
            for (int nh = 0; nh < 2; nh++) {
                uint32_t bh[4][2], bl[4][2];
#pragma unroll
                for (int j = 0; j < 4; j++) {
                    int rn = wN + (nh * 4 + j) * 8 + gID;
                    bh[j][0] = *(const uint32_t*)&Bh[rn * LDA + kb];
                    bh[j][1] = *(const uint32_t*)&Bh[rn * LDA + kb + 8];
                    bl[j][0] = *(const uint32_t*)&Bl[rn * LDA + kb];
                    bl[j][1] = *(const uint32_t*)&Bl[rn * LDA + kb + 8];
                }
#pragma unroll
                for (int p = 0; p < 3; p++)
#pragma unroll
                    for (int mt = 0; mt < 2; mt++)
#pragma unroll
                        for (int j = 0; j < 4; j++)
                            mma16816(acc[mt][nh * 4 + j],
                                     (p == 2) ? al[mt] : ah[mt],
                                     (p == 1) ? bl[j] : bh[j]);
            }
        }
        __syncthreads();
    }

    // epilogue
#pragma unroll
    for (int mt = 0; mt < 2; mt++)
#pragma unroll
        for (int nt = 0; nt < 8; nt++) {
            int i_ = wM + mt * 16 + gID;
            int j_ = wN + nt * 8 + thID * 2;
            float v0 = acc[mt][nt][0] + sbias[j_];
            float v1 = acc[mt][nt][1] + sbias[j_ + 1];
            float v2 = acc[mt][nt][2] + sbias[j_];
            float v3 = acc[mt][nt][3] + sbias[j_ + 1];
            if (ACT) {
                v0 = v0 > 0.f ? v0 : 0.01f * v0;
                v1 = v1 > 0.f ? v1 : 0.01f * v1;
                v2 = v2 > 0.f ? v2 : 0.01f * v2;
                v3 = v3 > 0.f ? v3 : 0.01f * v3;
            }
            if (MODE == 0) {
                long base = (long)b * strideY + (long)(i0 + i_) * ldY + j0 + j_;
                bf162 h2, l2;
                split2(v0, h2.x, l2.x); split2(v1, h2.y, l2.y);
                *(bf162*)&Yhi[base] = h2;
                *(bf162*)&Ylo[base] = l2;
                split2(v2, h2.x, l2.x); split2(v3, h2.y, l2.y);
                *(bf162*)&Yhi[base + 8L * ldY] = h2;
                *(bf162*)&Ylo[base + 8L * ldY] = l2;
            } else if (MODE == 1) {
                long c0 = ((long)b * 128 + j0 + j_) * 2049 + i0 + i_;
                Yf[c0] = v0;
                Yf[c0 + 2049] = v1;
                Yf[c0 + 8] = v2;
                Yf[c0 + 2049 + 8] = v3;
            } else {
                long base = (long)b * strideY + (long)(i0 + i_) * ldY + j0 + j_;
                *(__half2*)&Yh[base] = __float22half2_rn(make_float2(v0, v1));
                *(__half2*)&Yh[base + 8L * ldY] =
                    __float22half2_rn(make_float2(v2, v3));
            }
        }
}

// ---------------------------------------------------------------------------
// Fused attention: S AND AV in single fp16 HMMA (fp32 accumulate; S error
// ~6e-5 abs, w error softmax-cancelled). K and V double-buffered.
// ---------------------------------------------------------------------------
#define LDW 136
#define APL (128 * LDW * 2)                 // bytes per plane (34816)
#define ATT_SMEM (6 * APL + 256 * 4 + 128 * 4)

__global__ void __launch_bounds__(256, 1) attn_cp(
    const __half* __restrict__ QKf,   // [b][t][256]: q 0-127, k 128-255
    const __half* __restrict__ Vg,    // [b][m][t]
    bf16* __restrict__ Ahi, bf16* __restrict__ Alo)
{
    extern __shared__ __align__(16) char smem[];
    __half* Qp = (__half*)(smem);
    __half* Kp[2] = {(__half*)(smem + APL), (__half*)(smem + 2 * APL)};
    __half* Vp[2] = {(__half*)(smem + 3 * APL), (__half*)(smem + 4 * APL)};
    __half* Wp = (__half*)(smem + 5 * APL);
    float* rsP    = (float*)(smem + 6 * APL);   // [2][128]
    float* srecip = rsP + 256;
    const uint32_t sb = smem_u32(smem);

    const int tid = threadIdx.x, lane = tid & 31, wid = tid >> 5;
    const int gID = lane >> 2, thID = lane & 3;
    const int b = blockIdx.y, q0 = blockIdx.x * 128;
    const int wM = (wid >> 1) * 32, wN = (wid & 1) * 64;
    const float cdiag = 0.97790291308792045f;  // 1 - 1/sqrt(2048)

    auto fillp = [&](int plane, const __half* src, long base, int ld) {
#pragma unroll
        for (int u = 0; u < 8; u++) {
            int c = tid + u * 256;
            int r = c >> 4, off = (c & 15) * 16;
            uint32_t sa = sb + plane * APL + (r * LDW) * 2 + off;
            const char* ga = (const char*)src + (base + (long)r * ld) * 2 + off;
            CPA16(sa, ga);
        }
    };

    const long qkstr = (long)b * T_SZ * 256;
    const long vstr  = (long)b * 128 * T_SZ;
    fillp(0, QKf, qkstr + (long)q0 * 256, 256);        // Q
    fillp(1, QKf, qkstr + 128, 256);                   // K tile 0
    CPC();                                             // group: Q+K0
    fillp(3, Vg, vstr, T_SZ);                          // V tile 0
    CPC();                                             // group: V0
    if (tid < 256) rsP[tid] = 0.f;

    float accv[2][8][4];
#pragma unroll
    for (int mt = 0; mt < 2; mt++)
#pragma unroll
        for (int nt = 0; nt < 8; nt++)
#pragma unroll
            for (int e = 0; e < 4; e++) accv[mt][nt][e] = 0.f;

    for (int kt = 0; kt < 16; kt++) {
        const __half* Kc = Kp[kt & 1];
        const __half* Vc = Vp[kt & 1];

        CPW(1);            // K(kt) ready
        __syncthreads();   // visibility; W free from AV(kt-1)

        // ---- S = Q K^T (single fp16) ----
        float accs[2][8][4];
#pragma unroll
        for (int mt = 0; mt < 2; mt++)
#pragma unroll
            for (int nt = 0; nt < 8; nt++)
#pragma unroll
                for (int e = 0; e < 4; e++) accs[mt][nt][e] = 0.f;
#pragma unroll
        for (int ks = 0; ks < 8; ks++) {
            const int kb = ks * 16 + thID * 2;
            uint32_t ah[2][4], bh[8][2];
#pragma unroll
            for (int mt = 0; mt < 2; mt++) {
                int r = wM + mt * 16 + gID;
                ah[mt][0] = *(const uint32_t*)&Qp[r * LDW + kb];
                ah[mt][1] = *(const uint32_t*)&Qp[(r + 8) * LDW + kb];
                ah[mt][2] = *(const uint32_t*)&Qp[r * LDW + kb + 8];
                ah[mt][3] = *(const uint32_t*)&Qp[(r + 8) * LDW + kb + 8];
            }
#pragma unroll
            for (int nt = 0; nt < 8; nt++) {
                int rn = wN + nt * 8 + gID;
                bh[nt][0] = *(const uint32_t*)&Kc[rn * LDW + kb];
                bh[nt][1] = *(const uint32_t*)&Kc[rn * LDW + kb + 8];
            }
#pragma unroll
            for (int mt = 0; mt < 2; mt++)
#pragma unroll
                for (int nt = 0; nt < 8; nt++)
                    mma16816h(accs[mt][nt], ah[mt], bh[nt]);
        }
        if (kt + 1 < 16) {
            fillp(1 + ((kt + 1) & 1), QKf,
                  qkstr + (long)(kt + 1) * 128 * 256 + 128, 256);
            CPC();
        }

        // ---- w = exp(exp(S diag-adj)) -> fp16 W plane, fp32 rowsum ----
        float rp[2][2] = {{0.f, 0.f}, {0.f, 0.f}};
#pragma unroll
        for (int mt = 0; mt < 2; mt++)
#pragma unroll
            for (int nt = 0; nt < 8; nt++) {
                int ql = wM + mt * 16 + gID;
                int kl = wN + nt * 8 + thID * 2;
                int qi = q0 + ql, kk = kt * 128 + kl;
                float x0 = accs[mt][nt][0], x1 = accs[mt][nt][1];
                float x2 = accs[mt][nt][2], x3 = accs[mt][nt][3];
                if (qi == kk)         x0 *= cdiag;
                if (qi == kk + 1)     x1 *= cdiag;
                if (qi + 8 == kk)     x2 *= cdiag;
                if (qi + 8 == kk + 1) x3 *= cdiag;
                float w0 = __expf(__expf(x0));
                float w1 = __expf(__expf(x1));
                float w2 = __expf(__expf(x2));
                float w3 = __expf(__expf(x3));
                rp[mt][0] += w0 + w1;
                rp[mt][1] += w2 + w3;
                *(__half2*)&Wp[ql * LDW + kl] =
                    __float22half2_rn(make_float2(w0, w1));
                *(__half2*)&Wp[(ql + 8) * LDW + kl] =
                    __float22half2_rn(make_float2(w2, w3));
            }
#pragma unroll
        for (int mt = 0; mt < 2; mt++)
#pragma unroll
            for (int h = 0; h < 2; h++) {
                float s = rp[mt][h];
                s += __shfl_xor_sync(0xffffffffu, s, 1);
                s += __shfl_xor_sync(0xffffffffu, s, 2);
                if (thID == 0)
                    rsP[(wid & 1) * 128 + wM + mt * 16 + gID + h * 8] += s;
            }
        if (kt < 15) { CPW(1); } else { CPW(0); }   // V(kt) ready
        __syncthreads();                             // W visible

        // ---- AV += W V^T (single fp16) ----
#pragma unroll
        for (int ks = 0; ks < 8; ks++) {
            const int kb = ks * 16 + thID * 2;
            uint32_t ah[2][4], bh[8][2];
#pragma unroll
            for (int mt = 0; mt < 2; mt++) {
                int r = wM + mt * 16 + gID;
                ah[mt][0] = *(const uint32_t*)&Wp[r * LDW + kb];
                ah[mt][1] = *(const uint32_t*)&Wp[(r + 8) * LDW + kb];
                ah[mt][2] = *(const uint32_t*)&Wp[r * LDW + kb + 8];
                ah[mt][3] = *(const uint32_t*)&Wp[(r + 8) * LDW + kb + 8];
            }
#pragma unroll
            for (int nt = 0; nt < 8; nt++) {
                int rn = wN + nt * 8 + gID;
                bh[nt][0] = *(const uint32_t*)&Vc[rn * LDW + kb];
                bh[nt][1] = *(const uint32_t*)&Vc[rn * LDW + kb + 8];
            }
#pragma unroll
            for (int mt = 0; mt < 2; mt++)
#pragma unroll
                for (int nt = 0; nt < 8; nt++)
                    mma16816h(accv[mt][nt], ah[mt], bh[nt]);
        }
        if (kt + 1 < 16) {
            fillp(3 + ((kt + 1) & 1), Vg, vstr + (long)(kt + 1) * 128, T_SZ);
            CPC();
        }
    }
    __syncthreads();
    if (tid < 128) srecip[tid] = 1.0f / (rsP[tid] + rsP[128 + tid]);
    __syncthreads();

    // out[b][q][m] = AV[q][m] / rowsum[q]  (split bf16)
#pragma unroll
    for (int mt = 0; mt < 2; mt++)
#pragma unroll
        for (int nt = 0; nt < 8; nt++) {
            int i_ = wM + mt * 16 + gID;
            int j_ = wN + nt * 8 + thID * 2;
            float r0 = srecip[i_], r1 = srecip[i_ + 8];
            long base = ((long)b * T_SZ + q0 + i_) * 128 + j_;
            bf162 h2, l2;
            split2(accv[mt][nt][0] * r0, h2.x, l2.x);
            split2(accv[mt][nt][1] * r0, h2.y, l2.y);
            *(bf162*)&Ahi[base] = h2;
            *(bf162*)&Alo[base] = l2;
            split2(accv[mt][nt][2] * r1, h2.x, l2.x);
            split2(accv[mt][nt][3] * r1, h2.y, l2.y);
            *(bf162*)&Ahi[base + 8L * 128] = h2;
            *(bf162*)&Alo[base + 8L * 128] = l2;
        }
}

// ---------------------------------------------------------------------------
// Windowed branch (Tq=1 => uniform softmax => mean of value[...,33:2047]) + Wo
// ---------------------------------------------------------------------------
__global__ void __launch_bounds__(256) tail_kernel(
    const float* __restrict__ value,
    const float* __restrict__ Wo1, const float* __restrict__ bo1,
    const float* __restrict__ Wo2, const float* __restrict__ bo2,
    float* __restrict__ out)
{
    __shared__ float ex[128];
    __shared__ float hv[512];
    const int b = blockIdx.x, tid = threadIdx.x;
    const int w = tid >> 5, lane = tid & 31;

    for (int it = 0; it < 16; it++) {
        int m = it * 8 + w;
        const float* vp = value + ((long)b * M_SZ + m) * T_SZ;
        float s = 0.f;
        for (int k = 33 + lane; k < 2047; k += 32) s += vp[k];
#pragma unroll
        for (int o = 16; o; o >>= 1) s += __shfl_xor_sync(0xffffffffu, s, o);
        if (lane == 0) ex[m] = s * (1.0f / 2014.0f);
    }
    __syncthreads();
    for (int h = tid; h < 512; h += 256) {
        float s = bo1[h];
#pragma unroll 4
        for (int m = 0; m < 128; m++) s += Wo1[h * 128 + m] * ex[m];
        hv[h] = s;
    }
    __syncthreads();
    if (tid < 128) {
        float s = bo2[tid];
#pragma unroll 4
        for (int h = 0; h < 512; h++) s += Wo2[tid * 512 + h] * hv[h];
        s = s > 0.f ? s : 0.01f * s;
        out[((long)b * M_SZ + tid) * 2049 + 2048] = s;
    }
}

// ---------------------------------------------------------------------------
extern "C" void kernel_launch(void* const* d_in, const int* in_sizes, int n_in,
                              void* d_out, int out_size) {
    const int ofs = (n_in >= 15) ? 3 : 2;
    const float* pattern = (const float*)d_in[0];
    const float* value   = (const float*)d_in[1];
    const float* Wq1 = (const float*)d_in[ofs + 0];
    const float* bq1 = (const float*)d_in[ofs + 1];
    const float* Wq2 = (const float*)d_in[ofs + 2];
    const float* bq2 = (const float*)d_in[ofs + 3];
    const float* Wk1 = (const float*)d_in[ofs + 4];
    const float* bk1 = (const float*)d_in[ofs + 5];
    const float* Wk2 = (const float*)d_in[ofs + 6];
    const float* bk2 = (const float*)d_in[ofs + 7];
    const float* Wo1 = (const float*)d_in[ofs + 8];
    const float* bo1 = (const float*)d_in[ofs + 9];
    const float* Wo2 = (const float*)d_in[ofs + 10];
    const float* bo2 = (const float*)d_in[ofs + 11];
    float* out = (float*)d_out;

    bf16 *Phi, *Plo, *Hhi, *Hlo, *Athi, *Atlo;
    bf16 *W1h, *W1l, *W2h, *W2l, *Wo1h, *Wo1l, *Wo2h, *Wo2l;
    __half *QK, *Vh;
    float *bc1, *bc2;
    cudaGetSymbolAddress((void**)&Phi,  g_Phi);
    cudaGetSymbolAddress((void**)&Plo,  g_Plo);
    cudaGetSymbolAddress((void**)&Hhi,  g_Hhi);
    cudaGetSymbolAddress((void**)&Hlo,  g_Hlo);
    cudaGetSymbolAddress((void**)&QK,   g_QK);
    cudaGetSymbolAddress((void**)&Vh,   g_Vh);
    cudaGetSymbolAddress((void**)&Athi, g_Athi);
    cudaGetSymbolAddress((void**)&Atlo, g_Atlo);
    cudaGetSymbolAddress((void**)&W1h,  g_W1h);
    cudaGetSymbolAddress((void**)&W1l,  g_W1l);
    cudaGetSymbolAddress((void**)&W2h,  g_W2h);
    cudaGetSymbolAddress((void**)&W2l,  g_W2l);
    cudaGetSymbolAddress((void**)&Wo1h, g_Wo1h);
    cudaGetSymbolAddress((void**)&Wo1l, g_Wo1l);
    cudaGetSymbolAddress((void**)&Wo2h, g_Wo2h);
    cudaGetSymbolAddress((void**)&Wo2l, g_Wo2l);
    cudaGetSymbolAddress((void**)&bc1,  g_bcat1);
    cudaGetSymbolAddress((void**)&bc2,  g_bcat2);

    cudaFuncSetAttribute(gemm_cp<0,0>, cudaFuncAttributeMaxDynamicSharedMemorySize, GEMM_SMEM);
    cudaFuncSetAttribute(gemm_cp<1,2>, cudaFuncAttributeMaxDynamicSharedMemorySize, GEMM_SMEM);
    cudaFuncSetAttribute(gemm_cp<1,1>, cudaFuncAttributeMaxDynamicSharedMemorySize, GEMM_SMEM);
    cudaFuncSetAttribute(attn_cp,      cudaFuncAttributeMaxDynamicSharedMemorySize, ATT_SMEM);

    // conversions (3 launches)
    conv_T_split<<<dim3(64, 4, 16), 256>>>(pattern, Phi, Plo);
    conv_half<<<512, 256>>>(value, Vh, (long)B_SZ * 128 * T_SZ);
    conv_weights<<<128, 256>>>(Wq1, Wk1, Wq2, Wk2, Wo1, Wo2,
                               bq1, bk1, bq2, bk2,
                               W1h, W1l, W2h, W2l, Wo1h, Wo1l, Wo2h, Wo2l,
                               bc1, bc2);

    const long sPM = (long)T_SZ * 128;

    // #4: fused q+k layer-1: H[b][t][0:1024]
    gemm_cp<0,0><<<dim3(16, 8, 16), 256, GEMM_SMEM>>>(
        Phi, Plo, W1h, W1l, bc1, Hhi, Hlo, nullptr, nullptr,
        128, 128, sPM, 1024, (long)T_SZ * 1024, 0);
    // #5: merged layer-2 (q+k) -> fp16 QK[b][t][256]; k-block reads H cols 512+
    gemm_cp<1,2><<<dim3(16, 2, 16), 256, GEMM_SMEM>>>(
        Hhi, Hlo, W2h, W2l, bc2, nullptr, nullptr, nullptr, QK,
        512, 1024, (long)T_SZ * 1024, 256, (long)T_SZ * 256, 512);
    // #6: attention  (ncu -s 5 -c 1 profiles this launch)
    attn_cp<<<dim3(16, 16), 256, ATT_SMEM>>>(QK, Vh, Athi, Atlo);
    // #7, #8: output MLP
    gemm_cp<0,0><<<dim3(16, 4, 16), 256, GEMM_SMEM>>>(
        Athi, Atlo, Wo1h, Wo1l, bo1, Hhi, Hlo, nullptr, nullptr,
        128, 128, sPM, 512, (long)T_SZ * 512, 0);
    gemm_cp<1,1><<<dim3(16, 1, 16), 256, GEMM_SMEM>>>(
        Hhi, Hlo, Wo2h, Wo2l, bo2, nullptr, nullptr, out, nullptr,
        512, 512, (long)T_SZ * 512, 0, 0, 0);
    // #9: windowed branch -> out[..., 2048]
    tail_kernel<<<B_SZ, 256>>>(value, Wo1, bo1, Wo2, bo2, out);
}